// round 7
// baseline (speedup 1.0000x reference)
#include <cuda_runtime.h>
#include <cuda_bf16.h>
#include <math.h>

// ---------------------------------------------------------------------------
// GAT 3-layer forward on GB300.
//   feat = H_in @ W (+ fused el/er epilogue)  [128x128 8x8 SGEMM, fp32]
//   agg (warp-per-dst-node, CSR), paired-half shuffle reductions
//   CSR build overlapped with layer-1 GEMM on a second stream.
// ---------------------------------------------------------------------------

#define MAXN 50000
#define MAXE 800000

__device__ float g_feat[MAXN * 256];
__device__ float g_bufA[MAXN * 256];
__device__ float g_bufB[MAXN * 256];
__device__ float g_el[MAXN * 4];
__device__ float g_er[MAXN * 4];
__device__ float g_ew[MAXE * 4];
__device__ int   g_rowptr[MAXN + 1];
__device__ int   g_cursor[MAXN];
__device__ int   g_cnt[MAXN];
__device__ int   g_colsrc[MAXE];

// ---------------------------------------------------------------------------
// CSR build
// ---------------------------------------------------------------------------
__global__ void hist_kernel(const int* __restrict__ dst, int* __restrict__ cnt, int E) {
    int i = blockIdx.x * blockDim.x + threadIdx.x;
    if (i < E) atomicAdd(&cnt[dst[i]], 1);
}

__global__ void scan_kernel(const int* __restrict__ cnt, int* __restrict__ rowptr,
                            int* __restrict__ cursor, int N, int E) {
    __shared__ int sums[1024];
    int tid = threadIdx.x;
    int chunk = (N + 1023) >> 10;
    int start = tid * chunk;
    int end = min(start + chunk, N);
    int s = 0;
    for (int i = start; i < end; i++) s += cnt[i];
    sums[tid] = s;
    __syncthreads();
    for (int off = 1; off < 1024; off <<= 1) {
        int v = (tid >= off) ? sums[tid - off] : 0;
        __syncthreads();
        sums[tid] += v;
        __syncthreads();
    }
    int run = sums[tid] - s;
    for (int i = start; i < end; i++) {
        rowptr[i] = run;
        cursor[i] = run;
        run += cnt[i];
    }
    if (tid == 0) rowptr[N] = E;
}

__global__ void scatter_kernel(const int* __restrict__ src, const int* __restrict__ dst,
                               int* __restrict__ cursor, int* __restrict__ colsrc, int E) {
    int i = blockIdx.x * blockDim.x + threadIdx.x;
    if (i < E) {
        int p = atomicAdd(&cursor[dst[i]], 1);
        colsrc[p] = src[i];
    }
}

// ---------------------------------------------------------------------------
// SGEMM 128x128, BK=16, 256 threads, 8x8 microtile, double-buffered.
// Thread cols: {tx*4..+3} and {64+tx*4..+3} (each chunk within one head).
// Fused el/er epilogue for H=4 (heads 2*bx and 2*bx+1).
// ---------------------------------------------------------------------------
__global__ __launch_bounds__(256) void sgemm128_kernel(
    const float* __restrict__ A, const float* __restrict__ B, float* __restrict__ C,
    const float* __restrict__ al, const float* __restrict__ ar,
    float* __restrict__ el, float* __restrict__ er,
    int M, int K, int Nc) {
    __shared__ float As[2][16][128];
    __shared__ float Bs[2][16][128];
    const unsigned FULL = 0xffffffffu;
    const int t = threadIdx.x;
    const int m0 = blockIdx.y * 128;
    const int n0 = blockIdx.x * 128;
    const int ty = t >> 4;          // 0..15, rows ty*8..+7
    const int tx = t & 15;          // cols tx*4 and 64+tx*4
    const int arow = t >> 2;        // 0..63
    const int akc  = (t & 3) * 4;
    const int brow = t >> 4;        // 0..15
    const int bcol = (t & 15) * 8;  // 0..120

    const bool aval0 = (m0 + arow) < M;
    const bool aval1 = (m0 + arow + 64) < M;
    const float* Ap0 = A + (size_t)(m0 + arow) * K + akc;
    const float* Ap1 = A + (size_t)(m0 + arow + 64) * K + akc;
    const float* Bp  = B + (size_t)brow * Nc + n0 + bcol;

    float acc[8][8];
    #pragma unroll
    for (int i = 0; i < 8; i++)
        #pragma unroll
        for (int j = 0; j < 8; j++) acc[i][j] = 0.f;

    {
        float4 v0 = aval0 ? *(const float4*)Ap0 : make_float4(0.f, 0.f, 0.f, 0.f);
        float4 v1 = aval1 ? *(const float4*)Ap1 : make_float4(0.f, 0.f, 0.f, 0.f);
        float4 bv0 = *(const float4*)Bp;
        float4 bv1 = *(const float4*)(Bp + 4);
        As[0][akc + 0][arow] = v0.x; As[0][akc + 1][arow] = v0.y;
        As[0][akc + 2][arow] = v0.z; As[0][akc + 3][arow] = v0.w;
        As[0][akc + 0][arow + 64] = v1.x; As[0][akc + 1][arow + 64] = v1.y;
        As[0][akc + 2][arow + 64] = v1.z; As[0][akc + 3][arow + 64] = v1.w;
        *(float4*)&Bs[0][brow][bcol] = bv0;
        *(float4*)&Bs[0][brow][bcol + 4] = bv1;
    }
    __syncthreads();

    int buf = 0;
    for (int k0 = 16; k0 < K; k0 += 16) {
        float4 v0 = aval0 ? *(const float4*)(Ap0 + k0) : make_float4(0.f, 0.f, 0.f, 0.f);
        float4 v1 = aval1 ? *(const float4*)(Ap1 + k0) : make_float4(0.f, 0.f, 0.f, 0.f);
        float4 bv0 = *(const float4*)(Bp + (size_t)k0 * Nc);
        float4 bv1 = *(const float4*)(Bp + (size_t)k0 * Nc + 4);
        #pragma unroll
        for (int kk = 0; kk < 16; kk++) {
            float4 bA = *(float4*)&Bs[buf][kk][tx * 4];
            float4 bB = *(float4*)&Bs[buf][kk][64 + tx * 4];
            float4 a0 = *(float4*)&As[buf][kk][ty * 8];
            float4 a1 = *(float4*)&As[buf][kk][ty * 8 + 4];
            float av[8] = {a0.x, a0.y, a0.z, a0.w, a1.x, a1.y, a1.z, a1.w};
            #pragma unroll
            for (int i = 0; i < 8; i++) {
                acc[i][0] += av[i] * bA.x; acc[i][1] += av[i] * bA.y;
                acc[i][2] += av[i] * bA.z; acc[i][3] += av[i] * bA.w;
                acc[i][4] += av[i] * bB.x; acc[i][5] += av[i] * bB.y;
                acc[i][6] += av[i] * bB.z; acc[i][7] += av[i] * bB.w;
            }
        }
        int nb = buf ^ 1;
        As[nb][akc + 0][arow] = v0.x; As[nb][akc + 1][arow] = v0.y;
        As[nb][akc + 2][arow] = v0.z; As[nb][akc + 3][arow] = v0.w;
        As[nb][akc + 0][arow + 64] = v1.x; As[nb][akc + 1][arow + 64] = v1.y;
        As[nb][akc + 2][arow + 64] = v1.z; As[nb][akc + 3][arow + 64] = v1.w;
        *(float4*)&Bs[nb][brow][bcol] = bv0;
        *(float4*)&Bs[nb][brow][bcol + 4] = bv1;
        __syncthreads();
        buf = nb;
    }
    #pragma unroll
    for (int kk = 0; kk < 16; kk++) {
        float4 bA = *(float4*)&Bs[buf][kk][tx * 4];
        float4 bB = *(float4*)&Bs[buf][kk][64 + tx * 4];
        float4 a0 = *(float4*)&As[buf][kk][ty * 8];
        float4 a1 = *(float4*)&As[buf][kk][ty * 8 + 4];
        float av[8] = {a0.x, a0.y, a0.z, a0.w, a1.x, a1.y, a1.z, a1.w};
        #pragma unroll
        for (int i = 0; i < 8; i++) {
            acc[i][0] += av[i] * bA.x; acc[i][1] += av[i] * bA.y;
            acc[i][2] += av[i] * bA.z; acc[i][3] += av[i] * bA.w;
            acc[i][4] += av[i] * bB.x; acc[i][5] += av[i] * bB.y;
            acc[i][6] += av[i] * bB.z; acc[i][7] += av[i] * bB.w;
        }
    }

    #pragma unroll
    for (int i = 0; i < 8; i++) {
        int r = m0 + ty * 8 + i;
        if (r < M) {
            *(float4*)&C[(size_t)r * Nc + n0 + tx * 4] =
                make_float4(acc[i][0], acc[i][1], acc[i][2], acc[i][3]);
            *(float4*)&C[(size_t)r * Nc + n0 + 64 + tx * 4] =
                make_float4(acc[i][4], acc[i][5], acc[i][6], acc[i][7]);
        }
    }

    // --- fused el/er epilogue: heads hA = 2*bx, hB = 2*bx+1 ---
    // Each 16-lane half of a warp holds one row's 4-col chunk per head.
    // 4-step butterfly (8,4,2,1) stays within the 16-lane half.
    const int hA = blockIdx.x * 2;
    const int hB = hA + 1;
    float laA[4], raA[4], laB[4], raB[4];
    #pragma unroll
    for (int j = 0; j < 4; j++) {
        laA[j] = al[hA * 64 + tx * 4 + j];
        raA[j] = ar[hA * 64 + tx * 4 + j];
        laB[j] = al[hB * 64 + tx * 4 + j];
        raB[j] = ar[hB * 64 + tx * 4 + j];
    }
    #pragma unroll
    for (int i = 0; i < 8; i++) {
        float lA = acc[i][0] * laA[0] + acc[i][1] * laA[1] + acc[i][2] * laA[2] + acc[i][3] * laA[3];
        float rA = acc[i][0] * raA[0] + acc[i][1] * raA[1] + acc[i][2] * raA[2] + acc[i][3] * raA[3];
        float lB = acc[i][4] * laB[0] + acc[i][5] * laB[1] + acc[i][6] * laB[2] + acc[i][7] * laB[3];
        float rB = acc[i][4] * raB[0] + acc[i][5] * raB[1] + acc[i][6] * raB[2] + acc[i][7] * raB[3];
        #pragma unroll
        for (int o = 8; o; o >>= 1) {
            lA += __shfl_xor_sync(FULL, lA, o);
            rA += __shfl_xor_sync(FULL, rA, o);
            lB += __shfl_xor_sync(FULL, lB, o);
            rB += __shfl_xor_sync(FULL, rB, o);
        }
        int row = m0 + ty * 8 + i;
        if (tx == 0 && row < M) {
            el[(size_t)row * 4 + hA] = lA;
            er[(size_t)row * 4 + hA] = rA;
            el[(size_t)row * 4 + hB] = lB;
            er[(size_t)row * 4 + hB] = rB;
        }
    }
}

// ---------------------------------------------------------------------------
// SGEMM 128x64 (layer 3, H=1), double-buffered, fused el/er epilogue.
// ---------------------------------------------------------------------------
__global__ __launch_bounds__(256) void sgemm64_kernel(
    const float* __restrict__ A, const float* __restrict__ B, float* __restrict__ C,
    const float* __restrict__ al, const float* __restrict__ ar,
    float* __restrict__ el, float* __restrict__ er,
    int M, int K, int Nc) {
    __shared__ float As[2][16][128];
    __shared__ float Bs[2][16][64];
    const unsigned FULL = 0xffffffffu;
    const int t = threadIdx.x;
    const int m0 = blockIdx.y * 128;
    const int ty = t >> 4;
    const int tx = t & 15;
    const int arow = t >> 2;
    const int akc  = (t & 3) * 4;
    const int brow = t >> 4;
    const int bcol = (t & 15) * 4;

    const bool aval0 = (m0 + arow) < M;
    const bool aval1 = (m0 + arow + 64) < M;
    const float* Ap0 = A + (size_t)(m0 + arow) * K + akc;
    const float* Ap1 = A + (size_t)(m0 + arow + 64) * K + akc;
    const float* Bp  = B + (size_t)brow * Nc + bcol;

    float acc[8][4];
    #pragma unroll
    for (int i = 0; i < 8; i++)
        #pragma unroll
        for (int j = 0; j < 4; j++) acc[i][j] = 0.f;

    {
        float4 v0 = aval0 ? *(const float4*)Ap0 : make_float4(0.f, 0.f, 0.f, 0.f);
        float4 v1 = aval1 ? *(const float4*)Ap1 : make_float4(0.f, 0.f, 0.f, 0.f);
        float4 bv = *(const float4*)Bp;
        As[0][akc + 0][arow] = v0.x; As[0][akc + 1][arow] = v0.y;
        As[0][akc + 2][arow] = v0.z; As[0][akc + 3][arow] = v0.w;
        As[0][akc + 0][arow + 64] = v1.x; As[0][akc + 1][arow + 64] = v1.y;
        As[0][akc + 2][arow + 64] = v1.z; As[0][akc + 3][arow + 64] = v1.w;
        *(float4*)&Bs[0][brow][bcol] = bv;
    }
    __syncthreads();

    int buf = 0;
    for (int k0 = 16; k0 < K; k0 += 16) {
        float4 v0 = aval0 ? *(const float4*)(Ap0 + k0) : make_float4(0.f, 0.f, 0.f, 0.f);
        float4 v1 = aval1 ? *(const float4*)(Ap1 + k0) : make_float4(0.f, 0.f, 0.f, 0.f);
        float4 bv = *(const float4*)(Bp + (size_t)k0 * Nc);
        #pragma unroll
        for (int kk = 0; kk < 16; kk++) {
            float4 b4 = *(float4*)&Bs[buf][kk][tx * 4];
            float4 a0 = *(float4*)&As[buf][kk][ty * 8];
            float4 a1 = *(float4*)&As[buf][kk][ty * 8 + 4];
            float av[8] = {a0.x, a0.y, a0.z, a0.w, a1.x, a1.y, a1.z, a1.w};
            #pragma unroll
            for (int i = 0; i < 8; i++) {
                acc[i][0] += av[i] * b4.x;
                acc[i][1] += av[i] * b4.y;
                acc[i][2] += av[i] * b4.z;
                acc[i][3] += av[i] * b4.w;
            }
        }
        int nb = buf ^ 1;
        As[nb][akc + 0][arow] = v0.x; As[nb][akc + 1][arow] = v0.y;
        As[nb][akc + 2][arow] = v0.z; As[nb][akc + 3][arow] = v0.w;
        As[nb][akc + 0][arow + 64] = v1.x; As[nb][akc + 1][arow + 64] = v1.y;
        As[nb][akc + 2][arow + 64] = v1.z; As[nb][akc + 3][arow + 64] = v1.w;
        *(float4*)&Bs[nb][brow][bcol] = bv;
        __syncthreads();
        buf = nb;
    }
    #pragma unroll
    for (int kk = 0; kk < 16; kk++) {
        float4 b4 = *(float4*)&Bs[buf][kk][tx * 4];
        float4 a0 = *(float4*)&As[buf][kk][ty * 8];
        float4 a1 = *(float4*)&As[buf][kk][ty * 8 + 4];
        float av[8] = {a0.x, a0.y, a0.z, a0.w, a1.x, a1.y, a1.z, a1.w};
        #pragma unroll
        for (int i = 0; i < 8; i++) {
            acc[i][0] += av[i] * b4.x;
            acc[i][1] += av[i] * b4.y;
            acc[i][2] += av[i] * b4.z;
            acc[i][3] += av[i] * b4.w;
        }
    }
    #pragma unroll
    for (int i = 0; i < 8; i++) {
        int r = m0 + ty * 8 + i;
        if (r < M)
            *(float4*)&C[(size_t)r * Nc + tx * 4] =
                make_float4(acc[i][0], acc[i][1], acc[i][2], acc[i][3]);
    }
    // epilogue (H=1)
    float la0 = al[tx * 4], la1 = al[tx * 4 + 1], la2 = al[tx * 4 + 2], la3 = al[tx * 4 + 3];
    float ra0 = ar[tx * 4], ra1 = ar[tx * 4 + 1], ra2 = ar[tx * 4 + 2], ra3 = ar[tx * 4 + 3];
    #pragma unroll
    for (int i = 0; i < 8; i++) {
        float l = acc[i][0] * la0 + acc[i][1] * la1 + acc[i][2] * la2 + acc[i][3] * la3;
        float r = acc[i][0] * ra0 + acc[i][1] * ra1 + acc[i][2] * ra2 + acc[i][3] * ra3;
        #pragma unroll
        for (int o = 8; o; o >>= 1) {
            l += __shfl_xor_sync(FULL, l, o);
            r += __shfl_xor_sync(FULL, r, o);
        }
        int row = m0 + ty * 8 + i;
        if (tx == 0 && row < M) {
            el[row] = l;
            er[row] = r;
        }
    }
}

__device__ __forceinline__ float lrelu(float x) { return x > 0.f ? x : 0.2f * x; }

// ---------------------------------------------------------------------------
// Aggregation H=4, D=64: one warp per dst node.
// Paired-half reduction: 5 shuffles per head-pair; results land per-half.
// ---------------------------------------------------------------------------
template <bool RELU>
__global__ __launch_bounds__(256) void agg4_kernel(
    const float* __restrict__ feat, const float* __restrict__ el,
    const float* __restrict__ er, const float* __restrict__ bias,
    const int* __restrict__ rowptr, const int* __restrict__ colsrc,
    float* __restrict__ ew, float* __restrict__ out, int N) {
    const unsigned FULL = 0xffffffffu;
    int n = (blockIdx.x * blockDim.x + threadIdx.x) >> 5;
    int lane = threadIdx.x & 31;
    if (n >= N) return;
    const int base = rowptr[n];
    const int deg = rowptr[n + 1] - base;
    const bool lo = (lane < 16);

    float4 r4 = *(const float4*)&er[(size_t)n * 4];
    float s0 = 0.f, s1 = 0.f, s2 = 0.f, s3 = 0.f;

    for (int i0 = 0; i0 < deg; i0 += 32) {
        int i = i0 + lane;
        bool act = i < deg;
        int s = colsrc[base + (act ? i : 0)];
        float4 l4 = *(const float4*)&el[(size_t)s * 4];
        float w0 = __expf(lrelu(l4.x + r4.x));
        float w1 = __expf(lrelu(l4.y + r4.y));
        float w2 = __expf(lrelu(l4.z + r4.z));
        float w3 = __expf(lrelu(l4.w + r4.w));
        if (act) {
            *(float4*)&ew[(size_t)(base + i) * 4] = make_float4(w0, w1, w2, w3);
            s0 += w0; s1 += w1; s2 += w2; s3 += w3;
        }
    }
    // Paired reduction: after this, lanes<16 hold total s0 (s2), lanes>=16 s1 (s3).
    float tA = lo ? s0 : s1;
    float oA = lo ? s1 : s0;
    float tB = lo ? s2 : s3;
    float oB = lo ? s3 : s2;
    tA += __shfl_xor_sync(FULL, oA, 16);
    tB += __shfl_xor_sync(FULL, oB, 16);
    #pragma unroll
    for (int o = 8; o; o >>= 1) {
        tA += __shfl_xor_sync(FULL, tA, o);
        tB += __shfl_xor_sync(FULL, tB, o);
    }
    const float isA = 1.f / tA;   // lanes<16: head0; lanes>=16: head1
    const float isB = 1.f / tB;   // lanes<16: head2; lanes>=16: head3
    const int c0 = lane * 4, c1 = 128 + lane * 4;

    float4 a0 = make_float4(0.f, 0.f, 0.f, 0.f);
    float4 a1 = make_float4(0.f, 0.f, 0.f, 0.f);
    int i = 0;
    for (; i + 8 <= deg; i += 8) {
        int   sI[8];
        float wa[8], wb[8];
        #pragma unroll
        for (int u = 0; u < 8; u++) {
            sI[u] = colsrc[base + i + u];
            float4 w4 = *(const float4*)&ew[(size_t)(base + i + u) * 4];
            wa[u] = (lo ? w4.x : w4.y) * isA;
            wb[u] = (lo ? w4.z : w4.w) * isB;
        }
        #pragma unroll
        for (int u = 0; u < 8; u++) {
            const float* fs = feat + (size_t)sI[u] * 256;
            float4 f0 = *(const float4*)&fs[c0];
            float4 f1 = *(const float4*)&fs[c1];
            a0.x += f0.x * wa[u]; a0.y += f0.y * wa[u];
            a0.z += f0.z * wa[u]; a0.w += f0.w * wa[u];
            a1.x += f1.x * wb[u]; a1.y += f1.y * wb[u];
            a1.z += f1.z * wb[u]; a1.w += f1.w * wb[u];
        }
    }
    for (; i < deg; i++) {
        int s = colsrc[base + i];
        float4 w4 = *(const float4*)&ew[(size_t)(base + i) * 4];
        float wA = (lo ? w4.x : w4.y) * isA;
        float wB = (lo ? w4.z : w4.w) * isB;
        const float* fs = feat + (size_t)s * 256;
        float4 f0 = *(const float4*)&fs[c0];
        float4 f1 = *(const float4*)&fs[c1];
        a0.x += f0.x * wA; a0.y += f0.y * wA; a0.z += f0.z * wA; a0.w += f0.w * wA;
        a1.x += f1.x * wB; a1.y += f1.y * wB; a1.z += f1.z * wB; a1.w += f1.w * wB;
    }
    float4 b0 = *(const float4*)&bias[c0];
    float4 b1 = *(const float4*)&bias[c1];
    a0.x += b0.x; a0.y += b0.y; a0.z += b0.z; a0.w += b0.w;
    a1.x += b1.x; a1.y += b1.y; a1.z += b1.z; a1.w += b1.w;
    if (RELU) {
        a0.x = fmaxf(a0.x, 0.f); a0.y = fmaxf(a0.y, 0.f);
        a0.z = fmaxf(a0.z, 0.f); a0.w = fmaxf(a0.w, 0.f);
        a1.x = fmaxf(a1.x, 0.f); a1.y = fmaxf(a1.y, 0.f);
        a1.z = fmaxf(a1.z, 0.f); a1.w = fmaxf(a1.w, 0.f);
    }
    *(float4*)&out[(size_t)n * 256 + c0] = a0;
    *(float4*)&out[(size_t)n * 256 + c1] = a1;
}

// ---------------------------------------------------------------------------
// Aggregation H=1, D=64: one warp per dst node.
// ---------------------------------------------------------------------------
__global__ __launch_bounds__(256) void agg1_kernel(
    const float* __restrict__ feat, const float* __restrict__ el,
    const float* __restrict__ er, const float* __restrict__ bias,
    const int* __restrict__ rowptr, const int* __restrict__ colsrc,
    float* __restrict__ ew, float* __restrict__ out, int N) {
    const unsigned FULL = 0xffffffffu;
    int n = (blockIdx.x * blockDim.x + threadIdx.x) >> 5;
    int lane = threadIdx.x & 31;
    if (n >= N) return;
    const int base = rowptr[n];
    const int deg = rowptr[n + 1] - base;
    const float rn = er[n];

    float s0 = 0.f;
    for (int i0 = 0; i0 < deg; i0 += 32) {
        int i = i0 + lane;
        bool act = i < deg;
        int s = colsrc[base + (act ? i : 0)];
        float w = __expf(lrelu(el[s] + rn));
        if (act) { ew[base + i] = w; s0 += w; }
    }
    #pragma unroll
    for (int o = 16; o; o >>= 1) s0 += __shfl_xor_sync(FULL, s0, o);
    const float is = 1.f / s0;
    const int c = lane * 2;

    float2 a = make_float2(0.f, 0.f);
    int i = 0;
    for (; i + 8 <= deg; i += 8) {
        int   sI[8];
        float wv[8];
        #pragma unroll
        for (int u = 0; u < 8; u++) {
            sI[u] = colsrc[base + i + u];
            wv[u] = ew[base + i + u] * is;
        }
        #pragma unroll
        for (int u = 0; u < 8; u++) {
            float2 f = *(const float2*)&feat[(size_t)sI[u] * 64 + c];
            a.x += f.x * wv[u];
            a.y += f.y * wv[u];
        }
    }
    for (; i < deg; i++) {
        int s = colsrc[base + i];
        float w = ew[base + i] * is;
        float2 f = *(const float2*)&feat[(size_t)s * 64 + c];
        a.x += f.x * w;
        a.y += f.y * w;
    }
    a.x += bias[c];
    a.y += bias[c + 1];
    *(float2*)&out[(size_t)n * 64 + c] = a;
}

// ---------------------------------------------------------------------------
// kernel_launch
// ---------------------------------------------------------------------------
extern "C" void kernel_launch(void* const* d_in, const int* in_sizes, int n_in,
                              void* d_out, int out_size) {
    const float* features = (const float*)d_in[0];
    const int*   src      = (const int*)d_in[1];
    const int*   dst      = (const int*)d_in[2];
    const float* W1  = (const float*)d_in[3];
    const float* al1 = (const float*)d_in[4];
    const float* ar1 = (const float*)d_in[5];
    const float* b1  = (const float*)d_in[6];
    const float* W2  = (const float*)d_in[7];
    const float* al2 = (const float*)d_in[8];
    const float* ar2 = (const float*)d_in[9];
    const float* b2  = (const float*)d_in[10];
    const float* W3  = (const float*)d_in[11];
    const float* al3 = (const float*)d_in[12];
    const float* ar3 = (const float*)d_in[13];
    const float* b3  = (const float*)d_in[14];

    const int N = in_sizes[0] / 128;
    const int E = in_sizes[1];

    float *feat, *bufA, *bufB, *el, *er, *ew;
    int *rowptr, *cursor, *cnt, *colsrc;
    cudaGetSymbolAddress((void**)&feat,   g_feat);
    cudaGetSymbolAddress((void**)&bufA,   g_bufA);
    cudaGetSymbolAddress((void**)&bufB,   g_bufB);
    cudaGetSymbolAddress((void**)&el,     g_el);
    cudaGetSymbolAddress((void**)&er,     g_er);
    cudaGetSymbolAddress((void**)&ew,     g_ew);
    cudaGetSymbolAddress((void**)&rowptr, g_rowptr);
    cudaGetSymbolAddress((void**)&cursor, g_cursor);
    cudaGetSymbolAddress((void**)&cnt,    g_cnt);
    cudaGetSymbolAddress((void**)&colsrc, g_colsrc);

    static cudaStream_t s_aux = nullptr;
    static cudaEvent_t e_fork = nullptr, e_join = nullptr;
    if (s_aux == nullptr) {
        cudaStreamCreateWithFlags(&s_aux, cudaStreamNonBlocking);
        cudaEventCreateWithFlags(&e_fork, cudaEventDisableTiming);
        cudaEventCreateWithFlags(&e_join, cudaEventDisableTiming);
    }

    // --- CSR build on aux stream, overlapped with layer-1 GEMM ---
    cudaEventRecord(e_fork, 0);
    cudaStreamWaitEvent(s_aux, e_fork, 0);
    cudaMemsetAsync(cnt, 0, (size_t)N * sizeof(int), s_aux);
    hist_kernel<<<(E + 255) / 256, 256, 0, s_aux>>>(dst, cnt, E);
    scan_kernel<<<1, 1024, 0, s_aux>>>(cnt, rowptr, cursor, N, E);
    scatter_kernel<<<(E + 255) / 256, 256, 0, s_aux>>>(src, dst, cursor, colsrc, E);
    cudaEventRecord(e_join, s_aux);

    const int aggGrid = (N + 7) / 8;

    // --- Layer 1: IN=128 -> 256 ---
    {
        dim3 grid(2, (N + 127) / 128);
        sgemm128_kernel<<<grid, 256>>>(features, W1, feat, al1, ar1, el, er, N, 128, 256);
        cudaStreamWaitEvent(0, e_join, 0);
        agg4_kernel<true><<<aggGrid, 256>>>(feat, el, er, b1, rowptr, colsrc, ew, bufA, N);
    }
    // --- Layer 2: 256 -> 256 ---
    {
        dim3 grid(2, (N + 127) / 128);
        sgemm128_kernel<<<grid, 256>>>(bufA, W2, feat, al2, ar2, el, er, N, 256, 256);
        agg4_kernel<true><<<aggGrid, 256>>>(feat, el, er, b2, rowptr, colsrc, ew, bufB, N);
    }
    // --- Layer 3: 256 -> 64 (H=1) ---
    {
        dim3 grid(1, (N + 127) / 128);
        sgemm64_kernel<<<grid, 256>>>(bufB, W3, feat, al3, ar3, el, er, N, 256, 64);
        agg1_kernel<<<aggGrid, 256>>>(feat, el, er, b3, rowptr, colsrc, ew, (float*)d_out, N);
    }
}

// round 11
// speedup vs baseline: 1.0509x; 1.0509x over previous
#include <cuda_runtime.h>
#include <cuda_bf16.h>
#include <math.h>

// ---------------------------------------------------------------------------
// GAT 3-layer forward on GB300.
//   feat = H_in @ W (+ fused el/er epilogue)  [128x64 dbl-buffered SGEMM, fp32]
//   agg (warp-per-dst-node, CSR): edge weights staged in SMEM, late normalize
//   CSR build overlapped with layer-1 GEMM on a second stream.
// ---------------------------------------------------------------------------

#define MAXN 50000
#define MAXE 800000
#define SMAXD 96   // per-warp smem edge capacity; global fallback beyond

__device__ float g_feat[MAXN * 256];
__device__ float g_bufA[MAXN * 256];
__device__ float g_bufB[MAXN * 256];
__device__ float g_el[MAXN * 4];
__device__ float g_er[MAXN * 4];
__device__ float g_ew[MAXE * 4];
__device__ int   g_rowptr[MAXN + 1];
__device__ int   g_cursor[MAXN];
__device__ int   g_cnt[MAXN];
__device__ int   g_colsrc[MAXE];

// ---------------------------------------------------------------------------
// CSR build
// ---------------------------------------------------------------------------
__global__ void hist_kernel(const int* __restrict__ dst, int* __restrict__ cnt, int E) {
    int i = blockIdx.x * blockDim.x + threadIdx.x;
    if (i < E) atomicAdd(&cnt[dst[i]], 1);
}

__global__ void scan_kernel(const int* __restrict__ cnt, int* __restrict__ rowptr,
                            int* __restrict__ cursor, int N, int E) {
    __shared__ int sums[1024];
    int tid = threadIdx.x;
    int chunk = (N + 1023) >> 10;
    int start = tid * chunk;
    int end = min(start + chunk, N);
    int s = 0;
    for (int i = start; i < end; i++) s += cnt[i];
    sums[tid] = s;
    __syncthreads();
    for (int off = 1; off < 1024; off <<= 1) {
        int v = (tid >= off) ? sums[tid - off] : 0;
        __syncthreads();
        sums[tid] += v;
        __syncthreads();
    }
    int run = sums[tid] - s;
    for (int i = start; i < end; i++) {
        rowptr[i] = run;
        cursor[i] = run;
        run += cnt[i];
    }
    if (tid == 0) rowptr[N] = E;
}

__global__ void scatter_kernel(const int* __restrict__ src, const int* __restrict__ dst,
                               int* __restrict__ cursor, int* __restrict__ colsrc, int E) {
    int i = blockIdx.x * blockDim.x + threadIdx.x;
    if (i < E) {
        int p = atomicAdd(&cursor[dst[i]], 1);
        colsrc[p] = src[i];
    }
}

// ---------------------------------------------------------------------------
// SGEMM 128x64, BK=16, 256 threads, 8x4 microtile, double-buffered (round-4).
// Block column bx == head. Fused el/er epilogue.
// ---------------------------------------------------------------------------
__global__ __launch_bounds__(256) void sgemm_fused_kernel(
    const float* __restrict__ A, const float* __restrict__ B, float* __restrict__ C,
    const float* __restrict__ al, const float* __restrict__ ar,
    float* __restrict__ el, float* __restrict__ er,
    int M, int K, int Nc, int H) {
    __shared__ float As[2][16][128];
    __shared__ float Bs[2][16][64];
    const unsigned FULL = 0xffffffffu;
    const int t = threadIdx.x;
    const int m0 = blockIdx.y * 128;
    const int n0 = blockIdx.x * 64;
    const int head = blockIdx.x;
    const int ty = t >> 4;
    const int tx = t & 15;
    const int arow = t >> 2;
    const int akc  = (t & 3) * 4;
    const int brow = t >> 4;
    const int bcol = (t & 15) * 4;

    const bool aval0 = (m0 + arow) < M;
    const bool aval1 = (m0 + arow + 64) < M;
    const float* Ap0 = A + (size_t)(m0 + arow) * K + akc;
    const float* Ap1 = A + (size_t)(m0 + arow + 64) * K + akc;
    const float* Bp  = B + (size_t)brow * Nc + n0 + bcol;

    float acc[8][4];
    #pragma unroll
    for (int i = 0; i < 8; i++)
        #pragma unroll
        for (int j = 0; j < 4; j++) acc[i][j] = 0.f;

    {
        float4 v0 = aval0 ? *(const float4*)Ap0 : make_float4(0.f, 0.f, 0.f, 0.f);
        float4 v1 = aval1 ? *(const float4*)Ap1 : make_float4(0.f, 0.f, 0.f, 0.f);
        float4 bv = *(const float4*)Bp;
        As[0][akc + 0][arow] = v0.x; As[0][akc + 1][arow] = v0.y;
        As[0][akc + 2][arow] = v0.z; As[0][akc + 3][arow] = v0.w;
        As[0][akc + 0][arow + 64] = v1.x; As[0][akc + 1][arow + 64] = v1.y;
        As[0][akc + 2][arow + 64] = v1.z; As[0][akc + 3][arow + 64] = v1.w;
        *(float4*)&Bs[0][brow][bcol] = bv;
    }
    __syncthreads();

    int buf = 0;
    for (int k0 = 16; k0 < K; k0 += 16) {
        float4 v0 = aval0 ? *(const float4*)(Ap0 + k0) : make_float4(0.f, 0.f, 0.f, 0.f);
        float4 v1 = aval1 ? *(const float4*)(Ap1 + k0) : make_float4(0.f, 0.f, 0.f, 0.f);
        float4 bv = *(const float4*)(Bp + (size_t)k0 * Nc);
        #pragma unroll
        for (int kk = 0; kk < 16; kk++) {
            float4 b4 = *(float4*)&Bs[buf][kk][tx * 4];
            float4 a0 = *(float4*)&As[buf][kk][ty * 8];
            float4 a1 = *(float4*)&As[buf][kk][ty * 8 + 4];
            float av[8] = {a0.x, a0.y, a0.z, a0.w, a1.x, a1.y, a1.z, a1.w};
            #pragma unroll
            for (int i = 0; i < 8; i++) {
                acc[i][0] += av[i] * b4.x;
                acc[i][1] += av[i] * b4.y;
                acc[i][2] += av[i] * b4.z;
                acc[i][3] += av[i] * b4.w;
            }
        }
        int nb = buf ^ 1;
        As[nb][akc + 0][arow] = v0.x; As[nb][akc + 1][arow] = v0.y;
        As[nb][akc + 2][arow] = v0.z; As[nb][akc + 3][arow] = v0.w;
        As[nb][akc + 0][arow + 64] = v1.x; As[nb][akc + 1][arow + 64] = v1.y;
        As[nb][akc + 2][arow + 64] = v1.z; As[nb][akc + 3][arow + 64] = v1.w;
        *(float4*)&Bs[nb][brow][bcol] = bv;
        __syncthreads();
        buf = nb;
    }
    #pragma unroll
    for (int kk = 0; kk < 16; kk++) {
        float4 b4 = *(float4*)&Bs[buf][kk][tx * 4];
        float4 a0 = *(float4*)&As[buf][kk][ty * 8];
        float4 a1 = *(float4*)&As[buf][kk][ty * 8 + 4];
        float av[8] = {a0.x, a0.y, a0.z, a0.w, a1.x, a1.y, a1.z, a1.w};
        #pragma unroll
        for (int i = 0; i < 8; i++) {
            acc[i][0] += av[i] * b4.x;
            acc[i][1] += av[i] * b4.y;
            acc[i][2] += av[i] * b4.z;
            acc[i][3] += av[i] * b4.w;
        }
    }

    #pragma unroll
    for (int i = 0; i < 8; i++) {
        int r = m0 + ty * 8 + i;
        if (r < M) {
            float4 o = make_float4(acc[i][0], acc[i][1], acc[i][2], acc[i][3]);
            *(float4*)&C[(size_t)r * Nc + n0 + tx * 4] = o;
        }
    }
    // --- fused el/er epilogue ---
    const float* alh = al + head * 64 + tx * 4;
    const float* arh = ar + head * 64 + tx * 4;
    float la0 = alh[0], la1 = alh[1], la2 = alh[2], la3 = alh[3];
    float ra0 = arh[0], ra1 = arh[1], ra2 = arh[2], ra3 = arh[3];
    #pragma unroll
    for (int i = 0; i < 8; i++) {
        float l = acc[i][0] * la0 + acc[i][1] * la1 + acc[i][2] * la2 + acc[i][3] * la3;
        float r = acc[i][0] * ra0 + acc[i][1] * ra1 + acc[i][2] * ra2 + acc[i][3] * ra3;
        #pragma unroll
        for (int o = 8; o; o >>= 1) {
            l += __shfl_xor_sync(FULL, l, o);
            r += __shfl_xor_sync(FULL, r, o);
        }
        int row = m0 + ty * 8 + i;
        if (tx == 0 && row < M) {
            el[(size_t)row * H + head] = l;
            er[(size_t)row * H + head] = r;
        }
    }
}

__device__ __forceinline__ float lrelu(float x) { return x > 0.f ? x : 0.2f * x; }

// ---------------------------------------------------------------------------
// Aggregation H=4, D=64: one warp per dst node.
// Weights staged in SMEM (deg<=SMAXD), unnormalized accumulate, late scale.
// ---------------------------------------------------------------------------
template <bool RELU>
__global__ __launch_bounds__(256) void agg4_kernel(
    const float* __restrict__ feat, const float* __restrict__ el,
    const float* __restrict__ er, const float* __restrict__ bias,
    const int* __restrict__ rowptr, const int* __restrict__ colsrc,
    float* __restrict__ ew, float* __restrict__ out, int N) {
    __shared__ int   s_src[8][SMAXD];
    __shared__ float s_w[8][SMAXD * 4];
    const unsigned FULL = 0xffffffffu;
    const int wid = threadIdx.x >> 5;
    const int lane = threadIdx.x & 31;
    int n = (blockIdx.x * blockDim.x + threadIdx.x) >> 5;
    if (n >= N) return;
    const int base = rowptr[n];
    const int deg = rowptr[n + 1] - base;
    const bool lo = (lane < 16);
    const bool fast = (deg <= SMAXD);

    float4 r4 = *(const float4*)&er[(size_t)n * 4];
    float s0 = 0.f, s1 = 0.f, s2 = 0.f, s3 = 0.f;

    // Pass A: weights into smem (or global fallback); per-head partial sums
    for (int i0 = 0; i0 < deg; i0 += 32) {
        int i = i0 + lane;
        bool act = i < deg;
        int s = colsrc[base + (act ? i : 0)];
        float4 l4 = *(const float4*)&el[(size_t)s * 4];
        float w0 = __expf(lrelu(l4.x + r4.x));
        float w1 = __expf(lrelu(l4.y + r4.y));
        float w2 = __expf(lrelu(l4.z + r4.z));
        float w3 = __expf(lrelu(l4.w + r4.w));
        if (act) {
            if (fast) {
                s_src[wid][i] = s;
                *(float4*)&s_w[wid][i * 4] = make_float4(w0, w1, w2, w3);
            } else {
                *(float4*)&ew[(size_t)(base + i) * 4] = make_float4(w0, w1, w2, w3);
            }
            s0 += w0; s1 += w1; s2 += w2; s3 += w3;
        }
    }
    __syncwarp();

    // Paired-half reduction: lanes<16 end with (head0, head2), lanes>=16 (head1, head3)
    float tA = lo ? s0 : s1;
    float oA = lo ? s1 : s0;
    float tB = lo ? s2 : s3;
    float oB = lo ? s3 : s2;
    tA += __shfl_xor_sync(FULL, oA, 16);
    tB += __shfl_xor_sync(FULL, oB, 16);
    #pragma unroll
    for (int o = 8; o; o >>= 1) {
        tA += __shfl_xor_sync(FULL, tA, o);
        tB += __shfl_xor_sync(FULL, tB, o);
    }
    const float isA = (deg > 0) ? 1.f / tA : 0.f;
    const float isB = (deg > 0) ? 1.f / tB : 0.f;
    const int c0 = lane * 4, c1 = 128 + lane * 4;

    // Pass B: unnormalized weighted gather-accumulate
    float4 a0 = make_float4(0.f, 0.f, 0.f, 0.f);
    float4 a1 = make_float4(0.f, 0.f, 0.f, 0.f);
    if (fast) {
        int i = 0;
        for (; i + 8 <= deg; i += 8) {
            int   sI[8];
            float wa[8], wb[8];
            #pragma unroll
            for (int u = 0; u < 8; u++) {
                sI[u] = s_src[wid][i + u];
                float4 w4 = *(float4*)&s_w[wid][(i + u) * 4];
                wa[u] = lo ? w4.x : w4.y;
                wb[u] = lo ? w4.z : w4.w;
            }
            #pragma unroll
            for (int u = 0; u < 8; u++) {
                const float* fs = feat + (size_t)sI[u] * 256;
                float4 f0 = *(const float4*)&fs[c0];
                float4 f1 = *(const float4*)&fs[c1];
                a0.x += f0.x * wa[u]; a0.y += f0.y * wa[u];
                a0.z += f0.z * wa[u]; a0.w += f0.w * wa[u];
                a1.x += f1.x * wb[u]; a1.y += f1.y * wb[u];
                a1.z += f1.z * wb[u]; a1.w += f1.w * wb[u];
            }
        }
        for (; i < deg; i++) {
            int s = s_src[wid][i];
            float4 w4 = *(float4*)&s_w[wid][i * 4];
            float wA = lo ? w4.x : w4.y;
            float wB = lo ? w4.z : w4.w;
            const float* fs = feat + (size_t)s * 256;
            float4 f0 = *(const float4*)&fs[c0];
            float4 f1 = *(const float4*)&fs[c1];
            a0.x += f0.x * wA; a0.y += f0.y * wA; a0.z += f0.z * wA; a0.w += f0.w * wA;
            a1.x += f1.x * wB; a1.y += f1.y * wB; a1.z += f1.z * wB; a1.w += f1.w * wB;
        }
    } else {
        for (int i = 0; i < deg; i++) {
            int s = colsrc[base + i];
            float4 w4 = *(const float4*)&ew[(size_t)(base + i) * 4];
            float wA = lo ? w4.x : w4.y;
            float wB = lo ? w4.z : w4.w;
            const float* fs = feat + (size_t)s * 256;
            float4 f0 = *(const float4*)&fs[c0];
            float4 f1 = *(const float4*)&fs[c1];
            a0.x += f0.x * wA; a0.y += f0.y * wA; a0.z += f0.z * wA; a0.w += f0.w * wA;
            a1.x += f1.x * wB; a1.y += f1.y * wB; a1.z += f1.z * wB; a1.w += f1.w * wB;
        }
    }
    // Late normalization + bias (+relu)
    float4 b0 = *(const float4*)&bias[c0];
    float4 b1 = *(const float4*)&bias[c1];
    a0.x = a0.x * isA + b0.x; a0.y = a0.y * isA + b0.y;
    a0.z = a0.z * isA + b0.z; a0.w = a0.w * isA + b0.w;
    a1.x = a1.x * isB + b1.x; a1.y = a1.y * isB + b1.y;
    a1.z = a1.z * isB + b1.z; a1.w = a1.w * isB + b1.w;
    if (RELU) {
        a0.x = fmaxf(a0.x, 0.f); a0.y = fmaxf(a0.y, 0.f);
        a0.z = fmaxf(a0.z, 0.f); a0.w = fmaxf(a0.w, 0.f);
        a1.x = fmaxf(a1.x, 0.f); a1.y = fmaxf(a1.y, 0.f);
        a1.z = fmaxf(a1.z, 0.f); a1.w = fmaxf(a1.w, 0.f);
    }
    *(float4*)&out[(size_t)n * 256 + c0] = a0;
    *(float4*)&out[(size_t)n * 256 + c1] = a1;
}

// ---------------------------------------------------------------------------
// Aggregation H=1, D=64: one warp per dst node, smem-staged weights.
// ---------------------------------------------------------------------------
__global__ __launch_bounds__(256) void agg1_kernel(
    const float* __restrict__ feat, const float* __restrict__ el,
    const float* __restrict__ er, const float* __restrict__ bias,
    const int* __restrict__ rowptr, const int* __restrict__ colsrc,
    float* __restrict__ ew, float* __restrict__ out, int N) {
    __shared__ int   s_src[8][SMAXD];
    __shared__ float s_w[8][SMAXD];
    const unsigned FULL = 0xffffffffu;
    const int wid = threadIdx.x >> 5;
    const int lane = threadIdx.x & 31;
    int n = (blockIdx.x * blockDim.x + threadIdx.x) >> 5;
    if (n >= N) return;
    const int base = rowptr[n];
    const int deg = rowptr[n + 1] - base;
    const float rn = er[n];
    const bool fast = (deg <= SMAXD);

    float s0 = 0.f;
    for (int i0 = 0; i0 < deg; i0 += 32) {
        int i = i0 + lane;
        bool act = i < deg;
        int s = colsrc[base + (act ? i : 0)];
        float w = __expf(lrelu(el[s] + rn));
        if (act) {
            if (fast) { s_src[wid][i] = s; s_w[wid][i] = w; }
            else      { ew[base + i] = w; }
            s0 += w;
        }
    }
    __syncwarp();
    #pragma unroll
    for (int o = 16; o; o >>= 1) s0 += __shfl_xor_sync(FULL, s0, o);
    const float is = (deg > 0) ? 1.f / s0 : 0.f;
    const int c = lane * 2;

    float2 a = make_float2(0.f, 0.f);
    if (fast) {
        int i = 0;
        for (; i + 8 <= deg; i += 8) {
            int   sI[8];
            float wv[8];
            #pragma unroll
            for (int u = 0; u < 8; u++) {
                sI[u] = s_src[wid][i + u];
                wv[u] = s_w[wid][i + u];
            }
            #pragma unroll
            for (int u = 0; u < 8; u++) {
                float2 f = *(const float2*)&feat[(size_t)sI[u] * 64 + c];
                a.x += f.x * wv[u];
                a.y += f.y * wv[u];
            }
        }
        for (; i < deg; i++) {
            float w = s_w[wid][i];
            float2 f = *(const float2*)&feat[(size_t)s_src[wid][i] * 64 + c];
            a.x += f.x * w;
            a.y += f.y * w;
        }
    } else {
        for (int i = 0; i < deg; i++) {
            int s = colsrc[base + i];
            float w = ew[base + i];
            float2 f = *(const float2*)&feat[(size_t)s * 64 + c];
            a.x += f.x * w;
            a.y += f.y * w;
        }
    }
    a.x = a.x * is + bias[c];
    a.y = a.y * is + bias[c + 1];
    *(float2*)&out[(size_t)n * 64 + c] = a;
}

// ---------------------------------------------------------------------------
// kernel_launch
// ---------------------------------------------------------------------------
extern "C" void kernel_launch(void* const* d_in, const int* in_sizes, int n_in,
                              void* d_out, int out_size) {
    const float* features = (const float*)d_in[0];
    const int*   src      = (const int*)d_in[1];
    const int*   dst      = (const int*)d_in[2];
    const float* W1  = (const float*)d_in[3];
    const float* al1 = (const float*)d_in[4];
    const float* ar1 = (const float*)d_in[5];
    const float* b1  = (const float*)d_in[6];
    const float* W2  = (const float*)d_in[7];
    const float* al2 = (const float*)d_in[8];
    const float* ar2 = (const float*)d_in[9];
    const float* b2  = (const float*)d_in[10];
    const float* W3  = (const float*)d_in[11];
    const float* al3 = (const float*)d_in[12];
    const float* ar3 = (const float*)d_in[13];
    const float* b3  = (const float*)d_in[14];

    const int N = in_sizes[0] / 128;
    const int E = in_sizes[1];

    float *feat, *bufA, *bufB, *el, *er, *ew;
    int *rowptr, *cursor, *cnt, *colsrc;
    cudaGetSymbolAddress((void**)&feat,   g_feat);
    cudaGetSymbolAddress((void**)&bufA,   g_bufA);
    cudaGetSymbolAddress((void**)&bufB,   g_bufB);
    cudaGetSymbolAddress((void**)&el,     g_el);
    cudaGetSymbolAddress((void**)&er,     g_er);
    cudaGetSymbolAddress((void**)&ew,     g_ew);
    cudaGetSymbolAddress((void**)&rowptr, g_rowptr);
    cudaGetSymbolAddress((void**)&cursor, g_cursor);
    cudaGetSymbolAddress((void**)&cnt,    g_cnt);
    cudaGetSymbolAddress((void**)&colsrc, g_colsrc);

    static cudaStream_t s_aux = nullptr;
    static cudaEvent_t e_fork = nullptr, e_join = nullptr;
    if (s_aux == nullptr) {
        cudaStreamCreateWithFlags(&s_aux, cudaStreamNonBlocking);
        cudaEventCreateWithFlags(&e_fork, cudaEventDisableTiming);
        cudaEventCreateWithFlags(&e_join, cudaEventDisableTiming);
    }

    // --- CSR build on aux stream, overlapped with layer-1 GEMM ---
    cudaEventRecord(e_fork, 0);
    cudaStreamWaitEvent(s_aux, e_fork, 0);
    cudaMemsetAsync(cnt, 0, (size_t)N * sizeof(int), s_aux);
    hist_kernel<<<(E + 255) / 256, 256, 0, s_aux>>>(dst, cnt, E);
    scan_kernel<<<1, 1024, 0, s_aux>>>(cnt, rowptr, cursor, N, E);
    scatter_kernel<<<(E + 255) / 256, 256, 0, s_aux>>>(src, dst, cursor, colsrc, E);
    cudaEventRecord(e_join, s_aux);

    const int aggGrid = (N + 7) / 8;

    // --- Layer 1: IN=128 -> 256 ---
    {
        dim3 grid(4, (N + 127) / 128);
        sgemm_fused_kernel<<<grid, 256>>>(features, W1, feat, al1, ar1, el, er, N, 128, 256, 4);
        cudaStreamWaitEvent(0, e_join, 0);
        agg4_kernel<true><<<aggGrid, 256>>>(feat, el, er, b1, rowptr, colsrc, ew, bufA, N);
    }
    // --- Layer 2: 256 -> 256 ---
    {
        dim3 grid(4, (N + 127) / 128);
        sgemm_fused_kernel<<<grid, 256>>>(bufA, W2, feat, al2, ar2, el, er, N, 256, 256, 4);
        agg4_kernel<true><<<aggGrid, 256>>>(feat, el, er, b2, rowptr, colsrc, ew, bufB, N);
    }
    // --- Layer 3: 256 -> 64 (H=1) ---
    {
        dim3 grid(1, (N + 127) / 128);
        sgemm_fused_kernel<<<grid, 256>>>(bufB, W3, feat, al3, ar3, el, er, N, 256, 64, 1);
        agg1_kernel<<<aggGrid, 256>>>(feat, el, er, b3, rowptr, colsrc, ew, (float*)d_out, N);
    }
}

// round 12
// speedup vs baseline: 1.1364x; 1.0814x over previous
#include <cuda_runtime.h>
#include <cuda_bf16.h>
#include <cuda_fp16.h>
#include <math.h>

// ---------------------------------------------------------------------------
// GAT 3-layer forward on GB300.
//   feat = H_in @ W (+ fused el/er epilogue)  [128x64 dbl-buffered SGEMM, fp32]
//     -> feat stored FP16 (only consumed by gather-aggregate; logits stay fp32)
//   agg (warp-per-dst-node, CSR): edge weights staged in SMEM, late normalize
//   CSR build overlapped with layer-1 GEMM on a second stream.
// ---------------------------------------------------------------------------

#define MAXN 50000
#define MAXE 800000
#define SMAXD 96   // per-warp smem edge capacity; global fallback beyond

__device__ __half g_feat[MAXN * 256];
__device__ float  g_bufA[MAXN * 256];
__device__ float  g_bufB[MAXN * 256];
__device__ float  g_el[MAXN * 4];
__device__ float  g_er[MAXN * 4];
__device__ float  g_ew[MAXE * 4];
__device__ int    g_rowptr[MAXN + 1];
__device__ int    g_cursor[MAXN];
__device__ int    g_cnt[MAXN];
__device__ int    g_colsrc[MAXE];

// ---------------------------------------------------------------------------
// CSR build
// ---------------------------------------------------------------------------
__global__ void hist_kernel(const int* __restrict__ dst, int* __restrict__ cnt, int E) {
    int i = blockIdx.x * blockDim.x + threadIdx.x;
    if (i < E) atomicAdd(&cnt[dst[i]], 1);
}

__global__ void scan_kernel(const int* __restrict__ cnt, int* __restrict__ rowptr,
                            int* __restrict__ cursor, int N, int E) {
    __shared__ int sums[1024];
    int tid = threadIdx.x;
    int chunk = (N + 1023) >> 10;
    int start = tid * chunk;
    int end = min(start + chunk, N);
    int s = 0;
    for (int i = start; i < end; i++) s += cnt[i];
    sums[tid] = s;
    __syncthreads();
    for (int off = 1; off < 1024; off <<= 1) {
        int v = (tid >= off) ? sums[tid - off] : 0;
        __syncthreads();
        sums[tid] += v;
        __syncthreads();
    }
    int run = sums[tid] - s;
    for (int i = start; i < end; i++) {
        rowptr[i] = run;
        cursor[i] = run;
        run += cnt[i];
    }
    if (tid == 0) rowptr[N] = E;
}

__global__ void scatter_kernel(const int* __restrict__ src, const int* __restrict__ dst,
                               int* __restrict__ cursor, int* __restrict__ colsrc, int E) {
    int i = blockIdx.x * blockDim.x + threadIdx.x;
    if (i < E) {
        int p = atomicAdd(&cursor[dst[i]], 1);
        colsrc[p] = src[i];
    }
}

// ---------------------------------------------------------------------------
// SGEMM 128x64, BK=16, 256 threads, 8x4 microtile, double-buffered.
// Block column bx == head. C written as FP16. Fused fp32 el/er epilogue.
// ---------------------------------------------------------------------------
__global__ __launch_bounds__(256) void sgemm_fused_kernel(
    const float* __restrict__ A, const float* __restrict__ B, __half* __restrict__ C,
    const float* __restrict__ al, const float* __restrict__ ar,
    float* __restrict__ el, float* __restrict__ er,
    int M, int K, int Nc, int H) {
    __shared__ float As[2][16][128];
    __shared__ float Bs[2][16][64];
    const unsigned FULL = 0xffffffffu;
    const int t = threadIdx.x;
    const int m0 = blockIdx.y * 128;
    const int n0 = blockIdx.x * 64;
    const int head = blockIdx.x;
    const int ty = t >> 4;
    const int tx = t & 15;
    const int arow = t >> 2;
    const int akc  = (t & 3) * 4;
    const int brow = t >> 4;
    const int bcol = (t & 15) * 4;

    const bool aval0 = (m0 + arow) < M;
    const bool aval1 = (m0 + arow + 64) < M;
    const float* Ap0 = A + (size_t)(m0 + arow) * K + akc;
    const float* Ap1 = A + (size_t)(m0 + arow + 64) * K + akc;
    const float* Bp  = B + (size_t)brow * Nc + n0 + bcol;

    float acc[8][4];
    #pragma unroll
    for (int i = 0; i < 8; i++)
        #pragma unroll
        for (int j = 0; j < 4; j++) acc[i][j] = 0.f;

    {
        float4 v0 = aval0 ? *(const float4*)Ap0 : make_float4(0.f, 0.f, 0.f, 0.f);
        float4 v1 = aval1 ? *(const float4*)Ap1 : make_float4(0.f, 0.f, 0.f, 0.f);
        float4 bv = *(const float4*)Bp;
        As[0][akc + 0][arow] = v0.x; As[0][akc + 1][arow] = v0.y;
        As[0][akc + 2][arow] = v0.z; As[0][akc + 3][arow] = v0.w;
        As[0][akc + 0][arow + 64] = v1.x; As[0][akc + 1][arow + 64] = v1.y;
        As[0][akc + 2][arow + 64] = v1.z; As[0][akc + 3][arow + 64] = v1.w;
        *(float4*)&Bs[0][brow][bcol] = bv;
    }
    __syncthreads();

    int buf = 0;
    for (int k0 = 16; k0 < K; k0 += 16) {
        float4 v0 = aval0 ? *(const float4*)(Ap0 + k0) : make_float4(0.f, 0.f, 0.f, 0.f);
        float4 v1 = aval1 ? *(const float4*)(Ap1 + k0) : make_float4(0.f, 0.f, 0.f, 0.f);
        float4 bv = *(const float4*)(Bp + (size_t)k0 * Nc);
        #pragma unroll
        for (int kk = 0; kk < 16; kk++) {
            float4 b4 = *(float4*)&Bs[buf][kk][tx * 4];
            float4 a0 = *(float4*)&As[buf][kk][ty * 8];
            float4 a1 = *(float4*)&As[buf][kk][ty * 8 + 4];
            float av[8] = {a0.x, a0.y, a0.z, a0.w, a1.x, a1.y, a1.z, a1.w};
            #pragma unroll
            for (int i = 0; i < 8; i++) {
                acc[i][0] += av[i] * b4.x;
                acc[i][1] += av[i] * b4.y;
                acc[i][2] += av[i] * b4.z;
                acc[i][3] += av[i] * b4.w;
            }
        }
        int nb = buf ^ 1;
        As[nb][akc + 0][arow] = v0.x; As[nb][akc + 1][arow] = v0.y;
        As[nb][akc + 2][arow] = v0.z; As[nb][akc + 3][arow] = v0.w;
        As[nb][akc + 0][arow + 64] = v1.x; As[nb][akc + 1][arow + 64] = v1.y;
        As[nb][akc + 2][arow + 64] = v1.z; As[nb][akc + 3][arow + 64] = v1.w;
        *(float4*)&Bs[nb][brow][bcol] = bv;
        __syncthreads();
        buf = nb;
    }
    #pragma unroll
    for (int kk = 0; kk < 16; kk++) {
        float4 b4 = *(float4*)&Bs[buf][kk][tx * 4];
        float4 a0 = *(float4*)&As[buf][kk][ty * 8];
        float4 a1 = *(float4*)&As[buf][kk][ty * 8 + 4];
        float av[8] = {a0.x, a0.y, a0.z, a0.w, a1.x, a1.y, a1.z, a1.w};
        #pragma unroll
        for (int i = 0; i < 8; i++) {
            acc[i][0] += av[i] * b4.x;
            acc[i][1] += av[i] * b4.y;
            acc[i][2] += av[i] * b4.z;
            acc[i][3] += av[i] * b4.w;
        }
    }

    #pragma unroll
    for (int i = 0; i < 8; i++) {
        int r = m0 + ty * 8 + i;
        if (r < M) {
            __half2 h0 = __floats2half2_rn(acc[i][0], acc[i][1]);
            __half2 h1 = __floats2half2_rn(acc[i][2], acc[i][3]);
            uint2 pack;
            pack.x = *reinterpret_cast<unsigned*>(&h0);
            pack.y = *reinterpret_cast<unsigned*>(&h1);
            *(uint2*)&C[(size_t)r * Nc + n0 + tx * 4] = pack;
        }
    }
    // --- fused el/er epilogue (fp32 accumulators) ---
    const float* alh = al + head * 64 + tx * 4;
    const float* arh = ar + head * 64 + tx * 4;
    float la0 = alh[0], la1 = alh[1], la2 = alh[2], la3 = alh[3];
    float ra0 = arh[0], ra1 = arh[1], ra2 = arh[2], ra3 = arh[3];
    #pragma unroll
    for (int i = 0; i < 8; i++) {
        float l = acc[i][0] * la0 + acc[i][1] * la1 + acc[i][2] * la2 + acc[i][3] * la3;
        float r = acc[i][0] * ra0 + acc[i][1] * ra1 + acc[i][2] * ra2 + acc[i][3] * ra3;
        #pragma unroll
        for (int o = 8; o; o >>= 1) {
            l += __shfl_xor_sync(FULL, l, o);
            r += __shfl_xor_sync(FULL, r, o);
        }
        int row = m0 + ty * 8 + i;
        if (tx == 0 && row < M) {
            el[(size_t)row * H + head] = l;
            er[(size_t)row * H + head] = r;
        }
    }
}

__device__ __forceinline__ float lrelu(float x) { return x > 0.f ? x : 0.2f * x; }

__device__ __forceinline__ void h4_to_f4(const __half* p, float& f0, float& f1,
                                         float& f2, float& f3) {
    uint2 q = *(const uint2*)p;
    __half2 h0 = *reinterpret_cast<__half2*>(&q.x);
    __half2 h1 = *reinterpret_cast<__half2*>(&q.y);
    float2 a = __half22float2(h0);
    float2 b = __half22float2(h1);
    f0 = a.x; f1 = a.y; f2 = b.x; f3 = b.y;
}

// ---------------------------------------------------------------------------
// Aggregation H=4, D=64: one warp per dst node, fp16 feature gather.
// Weights staged in SMEM (deg<=SMAXD), unnormalized accumulate, late scale.
// ---------------------------------------------------------------------------
template <bool RELU>
__global__ __launch_bounds__(256) void agg4_kernel(
    const __half* __restrict__ feat, const float* __restrict__ el,
    const float* __restrict__ er, const float* __restrict__ bias,
    const int* __restrict__ rowptr, const int* __restrict__ colsrc,
    float* __restrict__ ew, float* __restrict__ out, int N) {
    __shared__ int   s_src[8][SMAXD];
    __shared__ float s_w[8][SMAXD * 4];
    const unsigned FULL = 0xffffffffu;
    const int wid = threadIdx.x >> 5;
    const int lane = threadIdx.x & 31;
    int n = (blockIdx.x * blockDim.x + threadIdx.x) >> 5;
    if (n >= N) return;
    const int base = rowptr[n];
    const int deg = rowptr[n + 1] - base;
    const bool lo = (lane < 16);
    const bool fast = (deg <= SMAXD);

    float4 r4 = *(const float4*)&er[(size_t)n * 4];
    float s0 = 0.f, s1 = 0.f, s2 = 0.f, s3 = 0.f;

    // Pass A: weights into smem (or global fallback); per-head partial sums
    for (int i0 = 0; i0 < deg; i0 += 32) {
        int i = i0 + lane;
        bool act = i < deg;
        int s = colsrc[base + (act ? i : 0)];
        float4 l4 = *(const float4*)&el[(size_t)s * 4];
        float w0 = __expf(lrelu(l4.x + r4.x));
        float w1 = __expf(lrelu(l4.y + r4.y));
        float w2 = __expf(lrelu(l4.z + r4.z));
        float w3 = __expf(lrelu(l4.w + r4.w));
        if (act) {
            if (fast) {
                s_src[wid][i] = s;
                *(float4*)&s_w[wid][i * 4] = make_float4(w0, w1, w2, w3);
            } else {
                *(float4*)&ew[(size_t)(base + i) * 4] = make_float4(w0, w1, w2, w3);
            }
            s0 += w0; s1 += w1; s2 += w2; s3 += w3;
        }
    }
    __syncwarp();

    // Paired-half reduction
    float tA = lo ? s0 : s1;
    float oA = lo ? s1 : s0;
    float tB = lo ? s2 : s3;
    float oB = lo ? s3 : s2;
    tA += __shfl_xor_sync(FULL, oA, 16);
    tB += __shfl_xor_sync(FULL, oB, 16);
    #pragma unroll
    for (int o = 8; o; o >>= 1) {
        tA += __shfl_xor_sync(FULL, tA, o);
        tB += __shfl_xor_sync(FULL, tB, o);
    }
    const float isA = (deg > 0) ? 1.f / tA : 0.f;
    const float isB = (deg > 0) ? 1.f / tB : 0.f;
    const int c0 = lane * 4, c1 = 128 + lane * 4;

    // Pass B: unnormalized weighted gather-accumulate (fp16 loads, fp32 acc)
    float4 a0 = make_float4(0.f, 0.f, 0.f, 0.f);
    float4 a1 = make_float4(0.f, 0.f, 0.f, 0.f);
    if (fast) {
        int i = 0;
        for (; i + 8 <= deg; i += 8) {
            int   sI[8];
            float wa[8], wb[8];
            #pragma unroll
            for (int u = 0; u < 8; u++) {
                sI[u] = s_src[wid][i + u];
                float4 w4 = *(float4*)&s_w[wid][(i + u) * 4];
                wa[u] = lo ? w4.x : w4.y;
                wb[u] = lo ? w4.z : w4.w;
            }
            #pragma unroll
            for (int u = 0; u < 8; u++) {
                const __half* fs = feat + (size_t)sI[u] * 256;
                float f0, f1, f2, f3, g0, g1, g2, g3;
                h4_to_f4(fs + c0, f0, f1, f2, f3);
                h4_to_f4(fs + c1, g0, g1, g2, g3);
                a0.x += f0 * wa[u]; a0.y += f1 * wa[u];
                a0.z += f2 * wa[u]; a0.w += f3 * wa[u];
                a1.x += g0 * wb[u]; a1.y += g1 * wb[u];
                a1.z += g2 * wb[u]; a1.w += g3 * wb[u];
            }
        }
        for (; i < deg; i++) {
            int s = s_src[wid][i];
            float4 w4 = *(float4*)&s_w[wid][i * 4];
            float wA = lo ? w4.x : w4.y;
            float wB = lo ? w4.z : w4.w;
            const __half* fs = feat + (size_t)s * 256;
            float f0, f1, f2, f3, g0, g1, g2, g3;
            h4_to_f4(fs + c0, f0, f1, f2, f3);
            h4_to_f4(fs + c1, g0, g1, g2, g3);
            a0.x += f0 * wA; a0.y += f1 * wA; a0.z += f2 * wA; a0.w += f3 * wA;
            a1.x += g0 * wB; a1.y += g1 * wB; a1.z += g2 * wB; a1.w += g3 * wB;
        }
    } else {
        for (int i = 0; i < deg; i++) {
            int s = colsrc[base + i];
            float4 w4 = *(const float4*)&ew[(size_t)(base + i) * 4];
            float wA = lo ? w4.x : w4.y;
            float wB = lo ? w4.z : w4.w;
            const __half* fs = feat + (size_t)s * 256;
            float f0, f1, f2, f3, g0, g1, g2, g3;
            h4_to_f4(fs + c0, f0, f1, f2, f3);
            h4_to_f4(fs + c1, g0, g1, g2, g3);
            a0.x += f0 * wA; a0.y += f1 * wA; a0.z += f2 * wA; a0.w += f3 * wA;
            a1.x += g0 * wB; a1.y += g1 * wB; a1.z += g2 * wB; a1.w += g3 * wB;
        }
    }
    // Late normalization + bias (+relu)
    float4 b0 = *(const float4*)&bias[c0];
    float4 b1 = *(const float4*)&bias[c1];
    a0.x = a0.x * isA + b0.x; a0.y = a0.y * isA + b0.y;
    a0.z = a0.z * isA + b0.z; a0.w = a0.w * isA + b0.w;
    a1.x = a1.x * isB + b1.x; a1.y = a1.y * isB + b1.y;
    a1.z = a1.z * isB + b1.z; a1.w = a1.w * isB + b1.w;
    if (RELU) {
        a0.x = fmaxf(a0.x, 0.f); a0.y = fmaxf(a0.y, 0.f);
        a0.z = fmaxf(a0.z, 0.f); a0.w = fmaxf(a0.w, 0.f);
        a1.x = fmaxf(a1.x, 0.f); a1.y = fmaxf(a1.y, 0.f);
        a1.z = fmaxf(a1.z, 0.f); a1.w = fmaxf(a1.w, 0.f);
    }
    *(float4*)&out[(size_t)n * 256 + c0] = a0;
    *(float4*)&out[(size_t)n * 256 + c1] = a1;
}

// ---------------------------------------------------------------------------
// Aggregation H=1, D=64: one warp per dst node, fp16 gather.
// ---------------------------------------------------------------------------
__global__ __launch_bounds__(256) void agg1_kernel(
    const __half* __restrict__ feat, const float* __restrict__ el,
    const float* __restrict__ er, const float* __restrict__ bias,
    const int* __restrict__ rowptr, const int* __restrict__ colsrc,
    float* __restrict__ ew, float* __restrict__ out, int N) {
    __shared__ int   s_src[8][SMAXD];
    __shared__ float s_w[8][SMAXD];
    const unsigned FULL = 0xffffffffu;
    const int wid = threadIdx.x >> 5;
    const int lane = threadIdx.x & 31;
    int n = (blockIdx.x * blockDim.x + threadIdx.x) >> 5;
    if (n >= N) return;
    const int base = rowptr[n];
    const int deg = rowptr[n + 1] - base;
    const float rn = er[n];
    const bool fast = (deg <= SMAXD);

    float s0 = 0.f;
    for (int i0 = 0; i0 < deg; i0 += 32) {
        int i = i0 + lane;
        bool act = i < deg;
        int s = colsrc[base + (act ? i : 0)];
        float w = __expf(lrelu(el[s] + rn));
        if (act) {
            if (fast) { s_src[wid][i] = s; s_w[wid][i] = w; }
            else      { ew[base + i] = w; }
            s0 += w;
        }
    }
    __syncwarp();
    #pragma unroll
    for (int o = 16; o; o >>= 1) s0 += __shfl_xor_sync(FULL, s0, o);
    const float is = (deg > 0) ? 1.f / s0 : 0.f;
    const int c = lane * 2;

    float2 a = make_float2(0.f, 0.f);
    if (fast) {
        int i = 0;
        for (; i + 8 <= deg; i += 8) {
            int   sI[8];
            float wv[8];
            #pragma unroll
            for (int u = 0; u < 8; u++) {
                sI[u] = s_src[wid][i + u];
                wv[u] = s_w[wid][i + u];
            }
            #pragma unroll
            for (int u = 0; u < 8; u++) {
                __half2 h = *(const __half2*)&feat[(size_t)sI[u] * 64 + c];
                float2 f = __half22float2(h);
                a.x += f.x * wv[u];
                a.y += f.y * wv[u];
            }
        }
        for (; i < deg; i++) {
            float w = s_w[wid][i];
            __half2 h = *(const __half2*)&feat[(size_t)s_src[wid][i] * 64 + c];
            float2 f = __half22float2(h);
            a.x += f.x * w;
            a.y += f.y * w;
        }
    } else {
        for (int i = 0; i < deg; i++) {
            int s = colsrc[base + i];
            float w = ew[base + i];
            __half2 h = *(const __half2*)&feat[(size_t)s * 64 + c];
            float2 f = __half22float2(h);
            a.x += f.x * w;
            a.y += f.y * w;
        }
    }
    a.x = a.x * is + bias[c];
    a.y = a.y * is + bias[c + 1];
    *(float2*)&out[(size_t)n * 64 + c] = a;
}

// ---------------------------------------------------------------------------
// kernel_launch
// ---------------------------------------------------------------------------
extern "C" void kernel_launch(void* const* d_in, const int* in_sizes, int n_in,
                              void* d_out, int out_size) {
    const float* features = (const float*)d_in[0];
    const int*   src      = (const int*)d_in[1];
    const int*   dst      = (const int*)d_in[2];
    const float* W1  = (const float*)d_in[3];
    const float* al1 = (const float*)d_in[4];
    const float* ar1 = (const float*)d_in[5];
    const float* b1  = (const float*)d_in[6];
    const float* W2  = (const float*)d_in[7];
    const float* al2 = (const float*)d_in[8];
    const float* ar2 = (const float*)d_in[9];
    const float* b2  = (const float*)d_in[10];
    const float* W3  = (const float*)d_in[11];
    const float* al3 = (const float*)d_in[12];
    const float* ar3 = (const float*)d_in[13];
    const float* b3  = (const float*)d_in[14];

    const int N = in_sizes[0] / 128;
    const int E = in_sizes[1];

    __half* feat;
    float *bufA, *bufB, *el, *er, *ew;
    int *rowptr, *cursor, *cnt, *colsrc;
    cudaGetSymbolAddress((void**)&feat,   g_feat);
    cudaGetSymbolAddress((void**)&bufA,   g_bufA);
    cudaGetSymbolAddress((void**)&bufB,   g_bufB);
    cudaGetSymbolAddress((void**)&el,     g_el);
    cudaGetSymbolAddress((void**)&er,     g_er);
    cudaGetSymbolAddress((void**)&ew,     g_ew);
    cudaGetSymbolAddress((void**)&rowptr, g_rowptr);
    cudaGetSymbolAddress((void**)&cursor, g_cursor);
    cudaGetSymbolAddress((void**)&cnt,    g_cnt);
    cudaGetSymbolAddress((void**)&colsrc, g_colsrc);

    static cudaStream_t s_aux = nullptr;
    static cudaEvent_t e_fork = nullptr, e_join = nullptr;
    if (s_aux == nullptr) {
        cudaStreamCreateWithFlags(&s_aux, cudaStreamNonBlocking);
        cudaEventCreateWithFlags(&e_fork, cudaEventDisableTiming);
        cudaEventCreateWithFlags(&e_join, cudaEventDisableTiming);
    }

    // --- CSR build on aux stream, overlapped with layer-1 GEMM ---
    cudaEventRecord(e_fork, 0);
    cudaStreamWaitEvent(s_aux, e_fork, 0);
    cudaMemsetAsync(cnt, 0, (size_t)N * sizeof(int), s_aux);
    hist_kernel<<<(E + 255) / 256, 256, 0, s_aux>>>(dst, cnt, E);
    scan_kernel<<<1, 1024, 0, s_aux>>>(cnt, rowptr, cursor, N, E);
    scatter_kernel<<<(E + 255) / 256, 256, 0, s_aux>>>(src, dst, cursor, colsrc, E);
    cudaEventRecord(e_join, s_aux);

    const int aggGrid = (N + 7) / 8;

    // --- Layer 1: IN=128 -> 256 ---
    {
        dim3 grid(4, (N + 127) / 128);
        sgemm_fused_kernel<<<grid, 256>>>(features, W1, feat, al1, ar1, el, er, N, 128, 256, 4);
        cudaStreamWaitEvent(0, e_join, 0);
        agg4_kernel<true><<<aggGrid, 256>>>(feat, el, er, b1, rowptr, colsrc, ew, bufA, N);
    }
    // --- Layer 2: 256 -> 256 ---
    {
        dim3 grid(4, (N + 127) / 128);
        sgemm_fused_kernel<<<grid, 256>>>(bufA, W2, feat, al2, ar2, el, er, N, 256, 256, 4);
        agg4_kernel<true><<<aggGrid, 256>>>(feat, el, er, b2, rowptr, colsrc, ew, bufB, N);
    }
    // --- Layer 3: 256 -> 64 (H=1) ---
    {
        dim3 grid(1, (N + 127) / 128);
        sgemm_fused_kernel<<<grid, 256>>>(bufB, W3, feat, al3, ar3, el, er, N, 256, 64, 1);
        agg1_kernel<<<aggGrid, 256>>>(feat, el, er, b3, rowptr, colsrc, ew, (float*)d_out, N);
    }
}

// round 14
// speedup vs baseline: 1.6439x; 1.4466x over previous
#include <cuda_runtime.h>
#include <cuda_bf16.h>
#include <cuda_fp16.h>
#include <mma.h>
#include <math.h>

using namespace nvcuda;

// ---------------------------------------------------------------------------
// GAT 3-layer forward on GB300.
//   feat = H_in @ W via HMMA (wmma fp16 x fp16 -> fp32), fused el/er epilogue
//   agg (warp-per-dst-node, CSR): smem-staged weights, late normalize,
//       fp16 feature gather, fp16 layer outputs (bufA/bufB)
//   CSR build overlapped with layer-1 GEMM on a second stream.
// ---------------------------------------------------------------------------

#define MAXN 50000
#define MAXE 800000
#define SMAXD 96   // per-warp smem edge capacity; global fallback beyond

__device__ __half g_feat[MAXN * 256];
__device__ __half g_bufA[MAXN * 256];
__device__ __half g_bufB[MAXN * 256];
__device__ float  g_el[MAXN * 4];
__device__ float  g_er[MAXN * 4];
__device__ float  g_ew[MAXE * 4];
__device__ int    g_rowptr[MAXN + 1];
__device__ int    g_cursor[MAXN];
__device__ int    g_cnt[MAXN];
__device__ int    g_colsrc[MAXE];

// ---------------------------------------------------------------------------
// CSR build
// ---------------------------------------------------------------------------
__global__ void hist_kernel(const int* __restrict__ dst, int* __restrict__ cnt, int E) {
    int i = blockIdx.x * blockDim.x + threadIdx.x;
    if (i < E) atomicAdd(&cnt[dst[i]], 1);
}

__global__ void scan_kernel(const int* __restrict__ cnt, int* __restrict__ rowptr,
                            int* __restrict__ cursor, int N, int E) {
    __shared__ int sums[1024];
    int tid = threadIdx.x;
    int chunk = (N + 1023) >> 10;
    int start = tid * chunk;
    int end = min(start + chunk, N);
    int s = 0;
    for (int i = start; i < end; i++) s += cnt[i];
    sums[tid] = s;
    __syncthreads();
    for (int off = 1; off < 1024; off <<= 1) {
        int v = (tid >= off) ? sums[tid - off] : 0;
        __syncthreads();
        sums[tid] += v;
        __syncthreads();
    }
    int run = sums[tid] - s;
    for (int i = start; i < end; i++) {
        rowptr[i] = run;
        cursor[i] = run;
        run += cnt[i];
    }
    if (tid == 0) rowptr[N] = E;
}

__global__ void scatter_kernel(const int* __restrict__ src, const int* __restrict__ dst,
                               int* __restrict__ cursor, int* __restrict__ colsrc, int E) {
    int i = blockIdx.x * blockDim.x + threadIdx.x;
    if (i < E) {
        int p = atomicAdd(&cursor[dst[i]], 1);
        colsrc[p] = src[i];
    }
}

// ---------------------------------------------------------------------------
// HMMA GEMM 128x64 block, 8 warps (4x2), warp tile 32x32 (2x2 wmma 16x16x16).
// A: TA (float or __half), W: fp32, both converted to fp16 at staging.
// C: fp16. Fused fp32 el/er epilogue (block column == one head).
// ---------------------------------------------------------------------------
template <typename TA>
__global__ __launch_bounds__(256) void hgemm_fused_kernel(
    const TA* __restrict__ A, const float* __restrict__ B, __half* __restrict__ C,
    const float* __restrict__ al, const float* __restrict__ arv,
    float* __restrict__ el, float* __restrict__ er,
    int M, int K, int Nc, int H) {
    constexpr int LDA = 24;   // halfs per A smem row (16 + 8 pad)
    constexpr int LDB = 72;   // halfs per B smem row (64 + 8 pad)
    constexpr int LDC = 72;   // floats per C smem row (64 + 8 pad)
    __shared__ __align__(16) float smemF[128 * LDC];
    __half* As = reinterpret_cast<__half*>(smemF);
    __half* Bs = As + 128 * LDA;
    float*  Cs = smemF;

    const int t = threadIdx.x;
    const int m0 = blockIdx.y * 128;
    const int n0 = blockIdx.x * 64;
    const int head = blockIdx.x;
    const int wid = t >> 5;
    const int wm = wid >> 1;   // 0..3 -> 32-row band
    const int wn = wid & 1;    // 0..1 -> 32-col band

    wmma::fragment<wmma::accumulator, 16, 16, 16, float> acc[2][2];
    #pragma unroll
    for (int i = 0; i < 2; i++)
        #pragma unroll
        for (int j = 0; j < 2; j++) wmma::fill_fragment(acc[i][j], 0.f);

    const int arow = t >> 1;           // 0..127
    const int acol = (t & 1) * 8;      // 0 or 8
    const int brow = t >> 4;           // 0..15
    const int bcol = (t & 15) * 4;     // 0..60

    for (int k0 = 0; k0 < K; k0 += 16) {
        // --- stage A (convert to fp16) ---
        union { __half h[8]; uint4 u; } ap;
        if (m0 + arow < M) {
            if constexpr (sizeof(TA) == 4) {
                float4 f0 = *(const float4*)&A[(size_t)(m0 + arow) * K + k0 + acol];
                float4 f1 = *(const float4*)&A[(size_t)(m0 + arow) * K + k0 + acol + 4];
                ap.h[0] = __float2half_rn(f0.x); ap.h[1] = __float2half_rn(f0.y);
                ap.h[2] = __float2half_rn(f0.z); ap.h[3] = __float2half_rn(f0.w);
                ap.h[4] = __float2half_rn(f1.x); ap.h[5] = __float2half_rn(f1.y);
                ap.h[6] = __float2half_rn(f1.z); ap.h[7] = __float2half_rn(f1.w);
            } else {
                ap.u = *(const uint4*)&A[(size_t)(m0 + arow) * K + k0 + acol];
            }
        } else {
            ap.u = make_uint4(0, 0, 0, 0);
        }
        *(uint4*)&As[arow * LDA + acol] = ap.u;

        // --- stage B (convert to fp16) ---
        {
            float4 bf = *(const float4*)&B[(size_t)(k0 + brow) * Nc + n0 + bcol];
            union { __half h[4]; uint2 u; } bp;
            bp.h[0] = __float2half_rn(bf.x); bp.h[1] = __float2half_rn(bf.y);
            bp.h[2] = __float2half_rn(bf.z); bp.h[3] = __float2half_rn(bf.w);
            *(uint2*)&Bs[brow * LDB + bcol] = bp.u;
        }
        __syncthreads();

        // --- mma ---
        wmma::fragment<wmma::matrix_a, 16, 16, 16, __half, wmma::row_major> afrag[2];
        wmma::fragment<wmma::matrix_b, 16, 16, 16, __half, wmma::row_major> bfrag[2];
        #pragma unroll
        for (int i = 0; i < 2; i++)
            wmma::load_matrix_sync(afrag[i], As + (wm * 32 + i * 16) * LDA, LDA);
        #pragma unroll
        for (int j = 0; j < 2; j++)
            wmma::load_matrix_sync(bfrag[j], Bs + wn * 32 + j * 16, LDB);
        #pragma unroll
        for (int i = 0; i < 2; i++)
            #pragma unroll
            for (int j = 0; j < 2; j++)
                wmma::mma_sync(acc[i][j], afrag[i], bfrag[j], acc[i][j]);
        __syncthreads();
    }

    // --- write accumulators to smem ---
    #pragma unroll
    for (int i = 0; i < 2; i++)
        #pragma unroll
        for (int j = 0; j < 2; j++)
            wmma::store_matrix_sync(Cs + (wm * 32 + i * 16) * LDC + wn * 32 + j * 16,
                                    acc[i][j], LDC, wmma::mem_row_major);
    __syncthreads();

    // --- epilogue: fp16 C store + fp32 el/er dot (2 threads per row) ---
    const int row = t >> 1;
    const int pair = t & 1;
    const int cbase = pair * 32;
    float l = 0.f, r = 0.f;
    __half2 hp[16];
    #pragma unroll
    for (int j = 0; j < 32; j += 2) {
        float c0v = Cs[row * LDC + cbase + j];
        float c1v = Cs[row * LDC + cbase + j + 1];
        hp[j >> 1] = __floats2half2_rn(c0v, c1v);
        l += c0v * al[head * 64 + cbase + j] + c1v * al[head * 64 + cbase + j + 1];
        r += c0v * arv[head * 64 + cbase + j] + c1v * arv[head * 64 + cbase + j + 1];
    }
    l += __shfl_xor_sync(0xffffffffu, l, 1);
    r += __shfl_xor_sync(0xffffffffu, r, 1);
    if (m0 + row < M) {
        uint4* dst = (uint4*)&C[(size_t)(m0 + row) * Nc + n0 + cbase];
        uint4* srcp = (uint4*)hp;
        dst[0] = srcp[0]; dst[1] = srcp[1]; dst[2] = srcp[2]; dst[3] = srcp[3];
        if (pair == 0) {
            el[(size_t)(m0 + row) * H + head] = l;
            er[(size_t)(m0 + row) * H + head] = r;
        }
    }
}

__device__ __forceinline__ float lrelu(float x) { return x > 0.f ? x : 0.2f * x; }

__device__ __forceinline__ void h4_to_f4(const __half* p, float& f0, float& f1,
                                         float& f2, float& f3) {
    uint2 q = *(const uint2*)p;
    __half2 h0 = *reinterpret_cast<__half2*>(&q.x);
    __half2 h1 = *reinterpret_cast<__half2*>(&q.y);
    float2 a = __half22float2(h0);
    float2 b = __half22float2(h1);
    f0 = a.x; f1 = a.y; f2 = b.x; f3 = b.y;
}

// ---------------------------------------------------------------------------
// Aggregation H=4, D=64: one warp per dst node, fp16 gather, fp16 output.
// ---------------------------------------------------------------------------
__global__ __launch_bounds__(256) void agg4_kernel(
    const __half* __restrict__ feat, const float* __restrict__ el,
    const float* __restrict__ er, const float* __restrict__ bias,
    const int* __restrict__ rowptr, const int* __restrict__ colsrc,
    float* __restrict__ ew, __half* __restrict__ out, int N) {
    __shared__ int   s_src[8][SMAXD];
    __shared__ float s_w[8][SMAXD * 4];
    const unsigned FULL = 0xffffffffu;
    const int wid = threadIdx.x >> 5;
    const int lane = threadIdx.x & 31;
    int n = (blockIdx.x * blockDim.x + threadIdx.x) >> 5;
    if (n >= N) return;
    const int base = rowptr[n];
    const int deg = rowptr[n + 1] - base;
    const bool lo = (lane < 16);
    const bool fast = (deg <= SMAXD);

    float4 r4 = *(const float4*)&er[(size_t)n * 4];
    float s0 = 0.f, s1 = 0.f, s2 = 0.f, s3 = 0.f;

    for (int i0 = 0; i0 < deg; i0 += 32) {
        int i = i0 + lane;
        bool act = i < deg;
        int s = colsrc[base + (act ? i : 0)];
        float4 l4 = *(const float4*)&el[(size_t)s * 4];
        float w0 = __expf(lrelu(l4.x + r4.x));
        float w1 = __expf(lrelu(l4.y + r4.y));
        float w2 = __expf(lrelu(l4.z + r4.z));
        float w3 = __expf(lrelu(l4.w + r4.w));
        if (act) {
            if (fast) {
                s_src[wid][i] = s;
                *(float4*)&s_w[wid][i * 4] = make_float4(w0, w1, w2, w3);
            } else {
                *(float4*)&ew[(size_t)(base + i) * 4] = make_float4(w0, w1, w2, w3);
            }
            s0 += w0; s1 += w1; s2 += w2; s3 += w3;
        }
    }
    __syncwarp();

    float tA = lo ? s0 : s1;
    float oA = lo ? s1 : s0;
    float tB = lo ? s2 : s3;
    float oB = lo ? s3 : s2;
    tA += __shfl_xor_sync(FULL, oA, 16);
    tB += __shfl_xor_sync(FULL, oB, 16);
    #pragma unroll
    for (int o = 8; o; o >>= 1) {
        tA += __shfl_xor_sync(FULL, tA, o);
        tB += __shfl_xor_sync(FULL, tB, o);
    }
    const float isA = (deg > 0) ? 1.f / tA : 0.f;
    const float isB = (deg > 0) ? 1.f / tB : 0.f;
    const int c0 = lane * 4, c1 = 128 + lane * 4;

    float4 a0 = make_float4(0.f, 0.f, 0.f, 0.f);
    float4 a1 = make_float4(0.f, 0.f, 0.f, 0.f);
    if (fast) {
        int i = 0;
        for (; i + 8 <= deg; i += 8) {
            int   sI[8];
            float wa[8], wb[8];
            #pragma unroll
            for (int u = 0; u < 8; u++) {
                sI[u] = s_src[wid][i + u];
                float4 w4 = *(float4*)&s_w[wid][(i + u) * 4];
                wa[u] = lo ? w4.x : w4.y;
                wb[u] = lo ? w4.z : w4.w;
            }
            #pragma unroll
            for (int u = 0; u < 8; u++) {
                const __half* fs = feat + (size_t)sI[u] * 256;
                float f0, f1, f2, f3, g0, g1, g2, g3;
                h4_to_f4(fs + c0, f0, f1, f2, f3);
                h4_to_f4(fs + c1, g0, g1, g2, g3);
                a0.x += f0 * wa[u]; a0.y += f1 * wa[u];
                a0.z += f2 * wa[u]; a0.w += f3 * wa[u];
                a1.x += g0 * wb[u]; a1.y += g1 * wb[u];
                a1.z += g2 * wb[u]; a1.w += g3 * wb[u];
            }
        }
        for (; i < deg; i++) {
            int s = s_src[wid][i];
            float4 w4 = *(float4*)&s_w[wid][i * 4];
            float wA = lo ? w4.x : w4.y;
            float wB = lo ? w4.z : w4.w;
            const __half* fs = feat + (size_t)s * 256;
            float f0, f1, f2, f3, g0, g1, g2, g3;
            h4_to_f4(fs + c0, f0, f1, f2, f3);
            h4_to_f4(fs + c1, g0, g1, g2, g3);
            a0.x += f0 * wA; a0.y += f1 * wA; a0.z += f2 * wA; a0.w += f3 * wA;
            a1.x += g0 * wB; a1.y += g1 * wB; a1.z += g2 * wB; a1.w += g3 * wB;
        }
    } else {
        for (int i = 0; i < deg; i++) {
            int s = colsrc[base + i];
            float4 w4 = *(const float4*)&ew[(size_t)(base + i) * 4];
            float wA = lo ? w4.x : w4.y;
            float wB = lo ? w4.z : w4.w;
            const __half* fs = feat + (size_t)s * 256;
            float f0, f1, f2, f3, g0, g1, g2, g3;
            h4_to_f4(fs + c0, f0, f1, f2, f3);
            h4_to_f4(fs + c1, g0, g1, g2, g3);
            a0.x += f0 * wA; a0.y += f1 * wA; a0.z += f2 * wA; a0.w += f3 * wA;
            a1.x += g0 * wB; a1.y += g1 * wB; a1.z += g2 * wB; a1.w += g3 * wB;
        }
    }
    float4 b0 = *(const float4*)&bias[c0];
    float4 b1 = *(const float4*)&bias[c1];
    a0.x = a0.x * isA + b0.x; a0.y = a0.y * isA + b0.y;
    a0.z = a0.z * isA + b0.z; a0.w = a0.w * isA + b0.w;
    a1.x = a1.x * isB + b1.x; a1.y = a1.y * isB + b1.y;
    a1.z = a1.z * isB + b1.z; a1.w = a1.w * isB + b1.w;
    // RELU always (agg4 used only for layers 1-2)
    a0.x = fmaxf(a0.x, 0.f); a0.y = fmaxf(a0.y, 0.f);
    a0.z = fmaxf(a0.z, 0.f); a0.w = fmaxf(a0.w, 0.f);
    a1.x = fmaxf(a1.x, 0.f); a1.y = fmaxf(a1.y, 0.f);
    a1.z = fmaxf(a1.z, 0.f); a1.w = fmaxf(a1.w, 0.f);
    union { __half2 h2[2]; uint2 u; } p0, p1;
    p0.h2[0] = __floats2half2_rn(a0.x, a0.y);
    p0.h2[1] = __floats2half2_rn(a0.z, a0.w);
    p1.h2[0] = __floats2half2_rn(a1.x, a1.y);
    p1.h2[1] = __floats2half2_rn(a1.z, a1.w);
    *(uint2*)&out[(size_t)n * 256 + c0] = p0.u;
    *(uint2*)&out[(size_t)n * 256 + c1] = p1.u;
}

// ---------------------------------------------------------------------------
// Aggregation H=1, D=64: one warp per dst node, fp16 gather, fp32 output.
// ---------------------------------------------------------------------------
__global__ __launch_bounds__(256) void agg1_kernel(
    const __half* __restrict__ feat, const float* __restrict__ el,
    const float* __restrict__ er, const float* __restrict__ bias,
    const int* __restrict__ rowptr, const int* __restrict__ colsrc,
    float* __restrict__ ew, float* __restrict__ out, int N) {
    __shared__ int   s_src[8][SMAXD];
    __shared__ float s_w[8][SMAXD];
    const unsigned FULL = 0xffffffffu;
    const int wid = threadIdx.x >> 5;
    const int lane = threadIdx.x & 31;
    int n = (blockIdx.x * blockDim.x + threadIdx.x) >> 5;
    if (n >= N) return;
    const int base = rowptr[n];
    const int deg = rowptr[n + 1] - base;
    const float rn = er[n];
    const bool fast = (deg <= SMAXD);

    float s0 = 0.f;
    for (int i0 = 0; i0 < deg; i0 += 32) {
        int i = i0 + lane;
        bool act = i < deg;
        int s = colsrc[base + (act ? i : 0)];
        float w = __expf(lrelu(el[s] + rn));
        if (act) {
            if (fast) { s_src[wid][i] = s; s_w[wid][i] = w; }
            else      { ew[base + i] = w; }
            s0 += w;
        }
    }
    __syncwarp();
    #pragma unroll
    for (int o = 16; o; o >>= 1) s0 += __shfl_xor_sync(FULL, s0, o);
    const float is = (deg > 0) ? 1.f / s0 : 0.f;
    const int c = lane * 2;

    float2 a = make_float2(0.f, 0.f);
    if (fast) {
        int i = 0;
        for (; i + 8 <= deg; i += 8) {
            int   sI[8];
            float wv[8];
            #pragma unroll
            for (int u = 0; u < 8; u++) {
                sI[u] = s_src[wid][i + u];
                wv[u] = s_w[wid][i + u];
            }
            #pragma unroll
            for (int u = 0; u < 8; u++) {
                __half2 h = *(const __half2*)&feat[(size_t)sI[u] * 64 + c];
                float2 f = __half22float2(h);
                a.x += f.x * wv[u];
                a.y += f.y * wv[u];
            }
        }
        for (; i < deg; i++) {
            float w = s_w[wid][i];
            __half2 h = *(const __half2*)&feat[(size_t)s_src[wid][i] * 64 + c];
            float2 f = __half22float2(h);
            a.x += f.x * w;
            a.y += f.y * w;
        }
    } else {
        for (int i = 0; i < deg; i++) {
            int s = colsrc[base + i];
            float w = ew[base + i];
            __half2 h = *(const __half2*)&feat[(size_t)s * 64 + c];
            float2 f = __half22float2(h);
            a.x += f.x * w;
            a.y += f.y * w;
        }
    }
    a.x = a.x * is + bias[c];
    a.y = a.y * is + bias[c + 1];
    *(float2*)&out[(size_t)n * 64 + c] = a;
}

// ---------------------------------------------------------------------------
// kernel_launch
// ---------------------------------------------------------------------------
extern "C" void kernel_launch(void* const* d_in, const int* in_sizes, int n_in,
                              void* d_out, int out_size) {
    const float* features = (const float*)d_in[0];
    const int*   src      = (const int*)d_in[1];
    const int*   dst      = (const int*)d_in[2];
    const float* W1  = (const float*)d_in[3];
    const float* al1 = (const float*)d_in[4];
    const float* ar1 = (const float*)d_in[5];
    const float* b1  = (const float*)d_in[6];
    const float* W2  = (const float*)d_in[7];
    const float* al2 = (const float*)d_in[8];
    const float* ar2 = (const float*)d_in[9];
    const float* b2  = (const float*)d_in[10];
    const float* W3  = (const float*)d_in[11];
    const float* al3 = (const float*)d_in[12];
    const float* ar3 = (const float*)d_in[13];
    const float* b3  = (const float*)d_in[14];

    const int N = in_sizes[0] / 128;
    const int E = in_sizes[1];

    __half *feat, *bufA, *bufB;
    float *el, *er, *ew;
    int *rowptr, *cursor, *cnt, *colsrc;
    cudaGetSymbolAddress((void**)&feat,   g_feat);
    cudaGetSymbolAddress((void**)&bufA,   g_bufA);
    cudaGetSymbolAddress((void**)&bufB,   g_bufB);
    cudaGetSymbolAddress((void**)&el,     g_el);
    cudaGetSymbolAddress((void**)&er,     g_er);
    cudaGetSymbolAddress((void**)&ew,     g_ew);
    cudaGetSymbolAddress((void**)&rowptr, g_rowptr);
    cudaGetSymbolAddress((void**)&cursor, g_cursor);
    cudaGetSymbolAddress((void**)&cnt,    g_cnt);
    cudaGetSymbolAddress((void**)&colsrc, g_colsrc);

    static cudaStream_t s_aux = nullptr;
    static cudaEvent_t e_fork = nullptr, e_join = nullptr;
    if (s_aux == nullptr) {
        cudaStreamCreateWithFlags(&s_aux, cudaStreamNonBlocking);
        cudaEventCreateWithFlags(&e_fork, cudaEventDisableTiming);
        cudaEventCreateWithFlags(&e_join, cudaEventDisableTiming);
    }

    // --- CSR build on aux stream, overlapped with layer-1 GEMM ---
    cudaEventRecord(e_fork, 0);
    cudaStreamWaitEvent(s_aux, e_fork, 0);
    cudaMemsetAsync(cnt, 0, (size_t)N * sizeof(int), s_aux);
    hist_kernel<<<(E + 255) / 256, 256, 0, s_aux>>>(dst, cnt, E);
    scan_kernel<<<1, 1024, 0, s_aux>>>(cnt, rowptr, cursor, N, E);
    scatter_kernel<<<(E + 255) / 256, 256, 0, s_aux>>>(src, dst, cursor, colsrc, E);
    cudaEventRecord(e_join, s_aux);

    const int aggGrid = (N + 7) / 8;
    const int mblocks = (N + 127) / 128;

    // --- Layer 1: IN=128 -> 256 ---
    {
        dim3 grid(4, mblocks);
        hgemm_fused_kernel<float><<<grid, 256>>>(features, W1, feat, al1, ar1, el, er,
                                                 N, 128, 256, 4);
        cudaStreamWaitEvent(0, e_join, 0);
        agg4_kernel<<<aggGrid, 256>>>(feat, el, er, b1, rowptr, colsrc, ew, bufA, N);
    }
    // --- Layer 2: 256 -> 256 ---
    {
        dim3 grid(4, mblocks);
        hgemm_fused_kernel<__half><<<grid, 256>>>(bufA, W2, feat, al2, ar2, el, er,
                                                  N, 256, 256, 4);
        agg4_kernel<<<aggGrid, 256>>>(feat, el, er, b2, rowptr, colsrc, ew, bufB, N);
    }
    // --- Layer 3: 256 -> 64 (H=1) ---
    {
        dim3 grid(1, mblocks);
        hgemm_fused_kernel<__half><<<grid, 256>>>(bufB, W3, feat, al3, ar3, el, er,
                                                  N, 256, 64, 1);
        agg1_kernel<<<aggGrid, 256>>>(feat, el, er, b3, rowptr, colsrc, ew, (float*)d_out, N);
    }
}

// round 16
// speedup vs baseline: 1.7289x; 1.0517x over previous
#include <cuda_runtime.h>
#include <cuda_bf16.h>
#include <cuda_fp16.h>
#include <mma.h>
#include <math.h>

using namespace nvcuda;

// ---------------------------------------------------------------------------
// GAT 3-layer forward on GB300.
//   feat = H_in @ W via HMMA (wmma, BK=32, reg double-buffer), fused el/er
//   agg (warp-per-dst-node, CSR): smem weights, late normalize,
//       lane-owns-8-cols fp16 gather (1 LDG.128/lane/edge)
//   CSR build overlapped with layer-1 GEMM on a second stream.
// ---------------------------------------------------------------------------

#define MAXN 50000
#define MAXE 800000
#define SMAXD 96

__device__ __half g_feat[MAXN * 256];
__device__ __half g_bufA[MAXN * 256];
__device__ __half g_bufB[MAXN * 256];
__device__ float  g_el[MAXN * 4];
__device__ float  g_er[MAXN * 4];
__device__ float  g_ew[MAXE * 4];
__device__ int    g_rowptr[MAXN + 1];
__device__ int    g_cursor[MAXN];
__device__ int    g_cnt[MAXN];
__device__ int    g_colsrc[MAXE];

// ---------------------------------------------------------------------------
// CSR build
// ---------------------------------------------------------------------------
__global__ void hist_kernel(const int* __restrict__ dst, int* __restrict__ cnt, int E) {
    int i = blockIdx.x * blockDim.x + threadIdx.x;
    if (i < E) atomicAdd(&cnt[dst[i]], 1);
}

__global__ void scan_kernel(const int* __restrict__ cnt, int* __restrict__ rowptr,
                            int* __restrict__ cursor, int N, int E) {
    __shared__ int sums[1024];
    int tid = threadIdx.x;
    int chunk = (N + 1023) >> 10;
    int start = tid * chunk;
    int end = min(start + chunk, N);
    int s = 0;
    for (int i = start; i < end; i++) s += cnt[i];
    sums[tid] = s;
    __syncthreads();
    for (int off = 1; off < 1024; off <<= 1) {
        int v = (tid >= off) ? sums[tid - off] : 0;
        __syncthreads();
        sums[tid] += v;
        __syncthreads();
    }
    int run = sums[tid] - s;
    for (int i = start; i < end; i++) {
        rowptr[i] = run;
        cursor[i] = run;
        run += cnt[i];
    }
    if (tid == 0) rowptr[N] = E;
}

__global__ void scatter_kernel(const int* __restrict__ src, const int* __restrict__ dst,
                               int* __restrict__ cursor, int* __restrict__ colsrc, int E) {
    int i = blockIdx.x * blockDim.x + threadIdx.x;
    if (i < E) {
        int p = atomicAdd(&cursor[dst[i]], 1);
        colsrc[p] = src[i];
    }
}

// ---------------------------------------------------------------------------
// HMMA GEMM 128x64 block, BK=32, 8 warps (4x2), warp tile 32x32.
// Register double-buffered staging (load next while mma current).
// A: TA (float or __half), W fp32 -> fp16 at staging. C fp16.
// Fused fp32 el/er epilogue (block column == one head).
// ---------------------------------------------------------------------------
template <typename TA>
__global__ __launch_bounds__(256) void hgemm_fused_kernel(
    const TA* __restrict__ A, const float* __restrict__ B, __half* __restrict__ C,
    const float* __restrict__ al, const float* __restrict__ arv,
    float* __restrict__ el, float* __restrict__ er,
    int M, int K, int Nc, int H) {
    constexpr int LDA = 40;   // halfs per A smem row (32 + 8 pad)
    constexpr int LDB = 72;   // halfs per B smem row (64 + 8 pad)
    constexpr int LDC = 72;   // floats per C smem row
    __shared__ __align__(16) float smemF[128 * LDC];          // 36864 B
    __half* As = reinterpret_cast<__half*>(smemF);            // [2][128*LDA]
    __half* Bs = As + 2 * 128 * LDA;                          // [2][32*LDB]
    float*  Cs = smemF;

    const int t = threadIdx.x;
    const int m0 = blockIdx.y * 128;
    const int n0 = blockIdx.x * 64;
    const int head = blockIdx.x;
    const int wid = t >> 5;
    const int wm = wid >> 1;
    const int wn = wid & 1;

    wmma::fragment<wmma::accumulator, 16, 16, 16, float> acc[2][2];
    #pragma unroll
    for (int i = 0; i < 2; i++)
        #pragma unroll
        for (int j = 0; j < 2; j++) wmma::fill_fragment(acc[i][j], 0.f);

    const int arow = t >> 1;          // 0..127
    const int acol = (t & 1) * 16;    // 0 or 16
    const int brow = t >> 3;          // 0..31
    const int bcol = (t & 7) * 8;     // 0..56
    const bool aval = (m0 + arow) < M;

    // helpers to load + convert one stage into registers
    auto loadA = [&](int k0, uint4& u0, uint4& u1) {
        if (aval) {
            if constexpr (sizeof(TA) == 4) {
                const float* ap = (const float*)A + (size_t)(m0 + arow) * K + k0 + acol;
                float4 f0 = *(const float4*)(ap + 0);
                float4 f1 = *(const float4*)(ap + 4);
                float4 f2 = *(const float4*)(ap + 8);
                float4 f3 = *(const float4*)(ap + 12);
                union { __half h[16]; uint4 u[2]; } p;
                p.h[0] = __float2half_rn(f0.x);  p.h[1] = __float2half_rn(f0.y);
                p.h[2] = __float2half_rn(f0.z);  p.h[3] = __float2half_rn(f0.w);
                p.h[4] = __float2half_rn(f1.x);  p.h[5] = __float2half_rn(f1.y);
                p.h[6] = __float2half_rn(f1.z);  p.h[7] = __float2half_rn(f1.w);
                p.h[8] = __float2half_rn(f2.x);  p.h[9] = __float2half_rn(f2.y);
                p.h[10] = __float2half_rn(f2.z); p.h[11] = __float2half_rn(f2.w);
                p.h[12] = __float2half_rn(f3.x); p.h[13] = __float2half_rn(f3.y);
                p.h[14] = __float2half_rn(f3.z); p.h[15] = __float2half_rn(f3.w);
                u0 = p.u[0]; u1 = p.u[1];
            } else {
                const __half* ap = (const __half*)A + (size_t)(m0 + arow) * K + k0 + acol;
                u0 = *(const uint4*)(ap + 0);
                u1 = *(const uint4*)(ap + 8);
            }
        } else {
            u0 = make_uint4(0, 0, 0, 0);
            u1 = make_uint4(0, 0, 0, 0);
        }
    };
    auto loadB = [&](int k0, uint4& u) {
        const float* bp = B + (size_t)(k0 + brow) * Nc + n0 + bcol;
        float4 f0 = *(const float4*)(bp + 0);
        float4 f1 = *(const float4*)(bp + 4);
        union { __half h[8]; uint4 uu; } p;
        p.h[0] = __float2half_rn(f0.x); p.h[1] = __float2half_rn(f0.y);
        p.h[2] = __float2half_rn(f0.z); p.h[3] = __float2half_rn(f0.w);
        p.h[4] = __float2half_rn(f1.x); p.h[5] = __float2half_rn(f1.y);
        p.h[6] = __float2half_rn(f1.z); p.h[7] = __float2half_rn(f1.w);
        u = p.uu;
    };
    auto storeStage = [&](int b, uint4 a0, uint4 a1, uint4 bu) {
        __half* abase = As + b * 128 * LDA + arow * LDA + acol;
        *(uint4*)(abase + 0) = a0;
        *(uint4*)(abase + 8) = a1;
        *(uint4*)(Bs + b * 32 * LDB + brow * LDB + bcol) = bu;
    };
    auto mmaStage = [&](int b) {
        #pragma unroll
        for (int kk = 0; kk < 32; kk += 16) {
            wmma::fragment<wmma::matrix_a, 16, 16, 16, __half, wmma::row_major> af[2];
            wmma::fragment<wmma::matrix_b, 16, 16, 16, __half, wmma::row_major> bf[2];
            #pragma unroll
            for (int i = 0; i < 2; i++)
                wmma::load_matrix_sync(af[i],
                    As + b * 128 * LDA + (wm * 32 + i * 16) * LDA + kk, LDA);
            #pragma unroll
            for (int j = 0; j < 2; j++)
                wmma::load_matrix_sync(bf[j],
                    Bs + b * 32 * LDB + kk * LDB + wn * 32 + j * 16, LDB);
            #pragma unroll
            for (int i = 0; i < 2; i++)
                #pragma unroll
                for (int j = 0; j < 2; j++)
                    wmma::mma_sync(acc[i][j], af[i], bf[j], acc[i][j]);
        }
    };

    // prologue
    {
        uint4 a0, a1, bu;
        loadA(0, a0, a1);
        loadB(0, bu);
        storeStage(0, a0, a1, bu);
    }
    __syncthreads();

    int buf = 0;
    for (int k0 = 32; k0 < K; k0 += 32) {
        uint4 a0, a1, bu;
        loadA(k0, a0, a1);
        loadB(k0, bu);
        mmaStage(buf);
        int nb = buf ^ 1;
        storeStage(nb, a0, a1, bu);
        __syncthreads();
        buf = nb;
    }
    mmaStage(buf);
    __syncthreads();   // all reads of As/Bs done before Cs overwrite

    #pragma unroll
    for (int i = 0; i < 2; i++)
        #pragma unroll
        for (int j = 0; j < 2; j++)
            wmma::store_matrix_sync(Cs + (wm * 32 + i * 16) * LDC + wn * 32 + j * 16,
                                    acc[i][j], LDC, wmma::mem_row_major);
    __syncthreads();

    // --- epilogue: fp16 C store + fp32 el/er dot (2 threads per row) ---
    const int row = t >> 1;
    const int pair = t & 1;
    const int cbase = pair * 32;
    float l = 0.f, r = 0.f;
    __half2 hp[16];
    #pragma unroll
    for (int j = 0; j < 32; j += 2) {
        float c0v = Cs[row * LDC + cbase + j];
        float c1v = Cs[row * LDC + cbase + j + 1];
        hp[j >> 1] = __floats2half2_rn(c0v, c1v);
        l += c0v * al[head * 64 + cbase + j] + c1v * al[head * 64 + cbase + j + 1];
        r += c0v * arv[head * 64 + cbase + j] + c1v * arv[head * 64 + cbase + j + 1];
    }
    l += __shfl_xor_sync(0xffffffffu, l, 1);
    r += __shfl_xor_sync(0xffffffffu, r, 1);
    if (m0 + row < M) {
        uint4* dst = (uint4*)&C[(size_t)(m0 + row) * Nc + n0 + cbase];
        uint4* srcp = (uint4*)hp;
        dst[0] = srcp[0]; dst[1] = srcp[1]; dst[2] = srcp[2]; dst[3] = srcp[3];
        if (pair == 0) {
            el[(size_t)(m0 + row) * H + head] = l;
            er[(size_t)(m0 + row) * H + head] = r;
        }
    }
}

__device__ __forceinline__ float lrelu(float x) { return x > 0.f ? x : 0.2f * x; }

// ---------------------------------------------------------------------------
// Aggregation H=4, D=64: one warp per dst node.
// Lane owns 8 contiguous cols (lane*8), head = lane>>3 -> 1 LDG.128/lane/edge.
// ---------------------------------------------------------------------------
__global__ __launch_bounds__(256) void agg4_kernel(
    const __half* __restrict__ feat, const float* __restrict__ el,
    const float* __restrict__ er, const float* __restrict__ bias,
    const int* __restrict__ rowptr, const int* __restrict__ colsrc,
    float* __restrict__ ew, __half* __restrict__ out, int N) {
    __shared__ int   s_src[8][SMAXD];
    __shared__ float s_w[8][SMAXD * 4];
    const unsigned FULL = 0xffffffffu;
    const int wid = threadIdx.x >> 5;
    const int lane = threadIdx.x & 31;
    int n = (blockIdx.x * blockDim.x + threadIdx.x) >> 5;
    if (n >= N) return;
    const int base = rowptr[n];
    const int deg = rowptr[n + 1] - base;
    const bool lo = (lane < 16);
    const bool fast = (deg <= SMAXD);
    const int h = lane >> 3;   // head owned by this lane

    float4 r4 = *(const float4*)&er[(size_t)n * 4];
    float s0 = 0.f, s1 = 0.f, s2 = 0.f, s3 = 0.f;

    // Pass A
    for (int i0 = 0; i0 < deg; i0 += 32) {
        int i = i0 + lane;
        bool act = i < deg;
        int s = colsrc[base + (act ? i : 0)];
        float4 l4 = *(const float4*)&el[(size_t)s * 4];
        float w0 = __expf(lrelu(l4.x + r4.x));
        float w1 = __expf(lrelu(l4.y + r4.y));
        float w2 = __expf(lrelu(l4.z + r4.z));
        float w3 = __expf(lrelu(l4.w + r4.w));
        if (act) {
            if (fast) {
                s_src[wid][i] = s;
                *(float4*)&s_w[wid][i * 4] = make_float4(w0, w1, w2, w3);
            } else {
                *(float4*)&ew[(size_t)(base + i) * 4] = make_float4(w0, w1, w2, w3);
            }
            s0 += w0; s1 += w1; s2 += w2; s3 += w3;
        }
    }
    __syncwarp();

    // Paired reduction: tA -> head0 (lanes<16) / head1 (lanes>=16); tB -> head2/3
    float tA = lo ? s0 : s1;
    float oA = lo ? s1 : s0;
    float tB = lo ? s2 : s3;
    float oB = lo ? s3 : s2;
    tA += __shfl_xor_sync(FULL, oA, 16);
    tB += __shfl_xor_sync(FULL, oB, 16);
    #pragma unroll
    for (int o = 8; o; o >>= 1) {
        tA += __shfl_xor_sync(FULL, tA, o);
        tB += __shfl_xor_sync(FULL, tB, o);
    }
    // per-lane normalizer for head h
    float selA = __shfl_sync(FULL, tA, (h & 1) ? 16 : 0);
    float selB = __shfl_sync(FULL, tB, (h & 1) ? 16 : 0);
    float ssum = (h < 2) ? selA : selB;
    const float is = (deg > 0) ? 1.f / ssum : 0.f;
    const int c = lane * 8;

    // Pass B: 1 x LDG.128 per lane per edge
    float a[8];
    #pragma unroll
    for (int k = 0; k < 8; k++) a[k] = 0.f;

    if (fast) {
        int i = 0;
        for (; i + 8 <= deg; i += 8) {
            uint4 q[8];
            float wv[8];
            #pragma unroll
            for (int u = 0; u < 8; u++) {
                int s = s_src[wid][i + u];
                wv[u] = s_w[wid][(i + u) * 4 + h];
                q[u] = *(const uint4*)&feat[(size_t)s * 256 + c];
            }
            #pragma unroll
            for (int u = 0; u < 8; u++) {
                __half2* hh = (__half2*)&q[u];
                #pragma unroll
                for (int j = 0; j < 4; j++) {
                    float2 f = __half22float2(hh[j]);
                    a[2 * j + 0] += f.x * wv[u];
                    a[2 * j + 1] += f.y * wv[u];
                }
            }
        }
        for (; i < deg; i++) {
            int s = s_src[wid][i];
            float w = s_w[wid][i * 4 + h];
            uint4 q = *(const uint4*)&feat[(size_t)s * 256 + c];
            __half2* hh = (__half2*)&q;
            #pragma unroll
            for (int j = 0; j < 4; j++) {
                float2 f = __half22float2(hh[j]);
                a[2 * j + 0] += f.x * w;
                a[2 * j + 1] += f.y * w;
            }
        }
    } else {
        for (int i = 0; i < deg; i++) {
            int s = colsrc[base + i];
            float w = ew[(size_t)(base + i) * 4 + h];
            uint4 q = *(const uint4*)&feat[(size_t)s * 256 + c];
            __half2* hh = (__half2*)&q;
            #pragma unroll
            for (int j = 0; j < 4; j++) {
                float2 f = __half22float2(hh[j]);
                a[2 * j + 0] += f.x * w;
                a[2 * j + 1] += f.y * w;
            }
        }
    }
    // Late normalize + bias + relu, fp16 store
    float4 b0 = *(const float4*)&bias[c];
    float4 b1 = *(const float4*)&bias[c + 4];
    a[0] = fmaxf(a[0] * is + b0.x, 0.f);
    a[1] = fmaxf(a[1] * is + b0.y, 0.f);
    a[2] = fmaxf(a[2] * is + b0.z, 0.f);
    a[3] = fmaxf(a[3] * is + b0.w, 0.f);
    a[4] = fmaxf(a[4] * is + b1.x, 0.f);
    a[5] = fmaxf(a[5] * is + b1.y, 0.f);
    a[6] = fmaxf(a[6] * is + b1.z, 0.f);
    a[7] = fmaxf(a[7] * is + b1.w, 0.f);
    union { __half2 h2[4]; uint4 u; } p;
    p.h2[0] = __floats2half2_rn(a[0], a[1]);
    p.h2[1] = __floats2half2_rn(a[2], a[3]);
    p.h2[2] = __floats2half2_rn(a[4], a[5]);
    p.h2[3] = __floats2half2_rn(a[6], a[7]);
    *(uint4*)&out[(size_t)n * 256 + c] = p.u;
}

// ---------------------------------------------------------------------------
// Aggregation H=1, D=64: one warp per dst node, fp16 gather, fp32 output.
// ---------------------------------------------------------------------------
__global__ __launch_bounds__(256) void agg1_kernel(
    const __half* __restrict__ feat, const float* __restrict__ el,
    const float* __restrict__ er, const float* __restrict__ bias,
    const int* __restrict__ rowptr, const int* __restrict__ colsrc,
    float* __restrict__ ew, float* __restrict__ out, int N) {
    __shared__ int   s_src[8][SMAXD];
    __shared__ float s_w[8][SMAXD];
    const unsigned FULL = 0xffffffffu;
    const int wid = threadIdx.x >> 5;
    const int lane = threadIdx.x & 31;
    int n = (blockIdx.x * blockDim.x + threadIdx.x) >> 5;
    if (n >= N) return;
    const int base = rowptr[n];
    const int deg = rowptr[n + 1] - base;
    const float rn = er[n];
    const bool fast = (deg <= SMAXD);

    float s0 = 0.f;
    for (int i0 = 0; i0 < deg; i0 += 32) {
        int i = i0 + lane;
        bool act = i < deg;
        int s = colsrc[base + (act ? i : 0)];
        float w = __expf(lrelu(el[s] + rn));
        if (act) {
            if (fast) { s_src[wid][i] = s; s_w[wid][i] = w; }
            else      { ew[base + i] = w; }
            s0 += w;
        }
    }
    __syncwarp();
    #pragma unroll
    for (int o = 16; o; o >>= 1) s0 += __shfl_xor_sync(FULL, s0, o);
    const float is = (deg > 0) ? 1.f / s0 : 0.f;
    const int c = lane * 2;

    float2 a = make_float2(0.f, 0.f);
    if (fast) {
        int i = 0;
        for (; i + 8 <= deg; i += 8) {
            int   sI[8];
            float wv[8];
            #pragma unroll
            for (int u = 0; u < 8; u++) {
                sI[u] = s_src[wid][i + u];
                wv[u] = s_w[wid][i + u];
            }
            #pragma unroll
            for (int u = 0; u < 8; u++) {
                __half2 hv = *(const __half2*)&feat[(size_t)sI[u] * 64 + c];
                float2 f = __half22float2(hv);
                a.x += f.x * wv[u];
                a.y += f.y * wv[u];
            }
        }
        for (; i < deg; i++) {
            float w = s_w[wid][i];
            __half2 hv = *(const __half2*)&feat[(size_t)s_src[wid][i] * 64 + c];
            float2 f = __half22float2(hv);
            a.x += f.x * w;
            a.y += f.y * w;
        }
    } else {
        for (int i = 0; i < deg; i++) {
            int s = colsrc[base + i];
            float w = ew[base + i];
            __half2 hv = *(const __half2*)&feat[(size_t)s * 64 + c];
            float2 f = __half22float2(hv);
            a.x += f.x * w;
            a.y += f.y * w;
        }
    }
    a.x = a.x * is + bias[c];
    a.y = a.y * is + bias[c + 1];
    *(float2*)&out[(size_t)n * 64 + c] = a;
}

// ---------------------------------------------------------------------------
// kernel_launch
// ---------------------------------------------------------------------------
extern "C" void kernel_launch(void* const* d_in, const int* in_sizes, int n_in,
                              void* d_out, int out_size) {
    const float* features = (const float*)d_in[0];
    const int*   src      = (const int*)d_in[1];
    const int*   dst      = (const int*)d_in[2];
    const float* W1  = (const float*)d_in[3];
    const float* al1 = (const float*)d_in[4];
    const float* ar1 = (const float*)d_in[5];
    const float* b1  = (const float*)d_in[6];
    const float* W2  = (const float*)d_in[7];
    const float* al2 = (const float*)d_in[8];
    const float* ar2 = (const float*)d_in[9];
    const float* b2  = (const float*)d_in[10];
    const float* W3  = (const float*)d_in[11];
    const float* al3 = (const float*)d_in[12];
    const float* ar3 = (const float*)d_in[13];
    const float* b3  = (const float*)d_in[14];

    const int N = in_sizes[0] / 128;
    const int E = in_sizes[1];

    __half *feat, *bufA, *bufB;
    float *el, *er, *ew;
    int *rowptr, *cursor, *cnt, *colsrc;
    cudaGetSymbolAddress((void**)&feat,   g_feat);
    cudaGetSymbolAddress((void**)&bufA,   g_bufA);
    cudaGetSymbolAddress((void**)&bufB,   g_bufB);
    cudaGetSymbolAddress((void**)&el,     g_el);
    cudaGetSymbolAddress((void**)&er,     g_er);
    cudaGetSymbolAddress((void**)&ew,     g_ew);
    cudaGetSymbolAddress((void**)&rowptr, g_rowptr);
    cudaGetSymbolAddress((void**)&cursor, g_cursor);
    cudaGetSymbolAddress((void**)&cnt,    g_cnt);
    cudaGetSymbolAddress((void**)&colsrc, g_colsrc);

    static cudaStream_t s_aux = nullptr;
    static cudaEvent_t e_fork = nullptr, e_join = nullptr;
    if (s_aux == nullptr) {
        cudaStreamCreateWithFlags(&s_aux, cudaStreamNonBlocking);
        cudaEventCreateWithFlags(&e_fork, cudaEventDisableTiming);
        cudaEventCreateWithFlags(&e_join, cudaEventDisableTiming);
    }

    // --- CSR build on aux stream, overlapped with layer-1 GEMM ---
    cudaEventRecord(e_fork, 0);
    cudaStreamWaitEvent(s_aux, e_fork, 0);
    cudaMemsetAsync(cnt, 0, (size_t)N * sizeof(int), s_aux);
    hist_kernel<<<(E + 255) / 256, 256, 0, s_aux>>>(dst, cnt, E);
    scan_kernel<<<1, 1024, 0, s_aux>>>(cnt, rowptr, cursor, N, E);
    scatter_kernel<<<(E + 255) / 256, 256, 0, s_aux>>>(src, dst, cursor, colsrc, E);
    cudaEventRecord(e_join, s_aux);

    const int aggGrid = (N + 7) / 8;
    const int mblocks = (N + 127) / 128;

    // --- Layer 1: IN=128 -> 256 ---
    {
        dim3 grid(4, mblocks);
        hgemm_fused_kernel<float><<<grid, 256>>>(features, W1, feat, al1, ar1, el, er,
                                                 N, 128, 256, 4);
        cudaStreamWaitEvent(0, e_join, 0);
        agg4_kernel<<<aggGrid, 256>>>(feat, el, er, b1, rowptr, colsrc, ew, bufA, N);
    }
    // --- Layer 2: 256 -> 256 ---
    {
        dim3 grid(4, mblocks);
        hgemm_fused_kernel<__half><<<grid, 256>>>(bufA, W2, feat, al2, ar2, el, er,
                                                  N, 256, 256, 4);
        agg4_kernel<<<aggGrid, 256>>>(feat, el, er, b2, rowptr, colsrc, ew, bufB, N);
    }
    // --- Layer 3: 256 -> 64 (H=1) ---
    {
        dim3 grid(1, mblocks);
        hgemm_fused_kernel<__half><<<grid, 256>>>(bufB, W3, feat, al3, ar3, el, er,
                                                  N, 256, 64, 1);
        agg1_kernel<<<aggGrid, 256>>>(feat, el, er, b3, rowptr, colsrc, ew, (float*)d_out, N);
    }
}